// round 13
// baseline (speedup 1.0000x reference)
#include <cuda_runtime.h>
#include <math.h>

#define NPAD  512
#define NPIX  (512*512)
#define ND    32
#define NTH   240
#define NINT  250
#define NIMG  256
#define MAXM  40960
#define KC    32
#define PI_F      3.14159265358979323846f
#define TWO_PI_F  6.28318530717958647692f
#define TWO_PI_D  6.283185307179586476925286766559

// ---------------- scratch (static device globals; no allocations) ----------
__device__ float2 d_Y[(size_t)ND*NPIX];   // FFT of padded windowed images
__device__ float2 d_Xf[NPIX];             // Wiener solution in freq domain
__device__ float2 d_T[NPIX];              // ifft intermediate
__device__ float  d_SoS[NPIX];
__device__ float  d_hA[(size_t)MAXM*128];
__device__ float  d_hB[(size_t)MAXM*128];
__device__ float  d_wfs[NTH];
__device__ float2 d_tw[256];              // e^{-i pi n / 256}
__device__ float  d_gw[256];              // Gaussian window 1D factors
__device__ double d_acc[3];               // data, tv, l1 accumulators

// ---------------- helpers ----------------
__device__ __forceinline__ float blockReduce(float v){
    __shared__ float red[32];
    int lane = threadIdx.x & 31, w = threadIdx.x >> 5;
    #pragma unroll
    for (int o = 16; o; o >>= 1) v += __shfl_down_sync(0xffffffffu, v, o);
    __syncthreads();
    if (lane == 0) red[w] = v;
    __syncthreads();
    float r = 0.f;
    if (w == 0){
        int nw = (blockDim.x + 31) >> 5;
        r = (lane < nw) ? red[lane] : 0.f;
        #pragma unroll
        for (int o = 16; o; o >>= 1) r += __shfl_down_sync(0xffffffffu, r, o);
    }
    __syncthreads();
    return r;  // valid on thread 0
}

// packed fp32x2 helpers (Blackwell f32x2 pipe; per-lane .rn rounding)
__device__ __forceinline__ unsigned long long pk2(float lo, float hi){
    unsigned long long r;
    asm("mov.b64 %0, {%1, %2};" : "=l"(r) : "f"(lo), "f"(hi));
    return r;
}
__device__ __forceinline__ unsigned long long fma2(unsigned long long a,
                                                   unsigned long long b,
                                                   unsigned long long c){
    unsigned long long d;
    asm("fma.rn.f32x2 %0, %1, %2, %3;" : "=l"(d) : "l"(a), "l"(b), "l"(c));
    return d;
}
__device__ __forceinline__ void upk2(unsigned long long v, float& lo, float& hi){
    asm("mov.b64 {%0, %1}, %2;" : "=f"(lo), "=f"(hi) : "l"(v));
}

// 1D interpolation over the 240-point theta grid (matches reference _interp1d)
__device__ __forceinline__ float interp_wf(float xn, const float* wf){
    const double step = TWO_PI_D / 239.0;
    const float dxg = (float)step;
    float t = xn / dxg;
    int fi = (int)floorf(t); fi = fi < 0 ? 0 : (fi > 239 ? 239 : fi);
    int ci = (int)ceilf(t);  ci = ci < 0 ? 0 : (ci > 239 ? 239 : ci);
    float yc = wf[ci];
    if (ci == fi) return yc;
    float yf = wf[fi];
    float xf = (float)((double)fi * step);
    float xc = (float)((double)ci * step);
    return yf + (yc - yf) * (xn - xf) / (xc - xf);
}

// Stockham radix-2 512-point FFT with shared twiddle table. 128 lanes/line.
__device__ __forceinline__ float2* fft512t(float2* a, float2* b,
                                           const float2* tw, int lane, bool inv){
    float2* src = a; float2* dst = b;
    #pragma unroll
    for (int s = 0; s < 9; s++){
        int m = 1 << s;
        __syncthreads();
        #pragma unroll
        for (int h = 0; h < 2; h++){
            int t = lane + h * 128;          // butterfly index 0..255
            int j = t >> s;
            int k = t & (m - 1);
            float2 c0 = src[j*m + k];
            float2 c1 = src[j*m + k + 256];
            float2 w = tw[t & ~(m - 1)];     // e^{-i pi (j<<s) / 256}
            float wy = inv ? -w.y : w.y;
            float dx = c0.x - c1.x, dy = c0.y - c1.y;
            dst[2*j*m + k]     = make_float2(c0.x + c1.x, c0.y + c1.y);
            dst[2*j*m + m + k] = make_float2(w.x*dx - wy*dy, w.x*dy + wy*dx);
        }
        float2* tmp = src; src = dst; dst = tmp;
    }
    __syncthreads();
    return src;
}

// ---------------- kernels ----------------
// SoS fill + (block 0) twiddle/window/accumulator init
__global__ void k_prep(){
    int p = blockIdx.x * 256 + threadIdx.x;
    d_SoS[p] = 1499.363f;
    if (blockIdx.x == 0){
        int n = threadIdx.x;
        float s, c;
        sincosf(PI_F * (float)n / 256.f, &s, &c);
        d_tw[n] = make_float2(c, -s);
        double ax  = (double)n - 127.5;
        double sig = 37.5 / sqrt(2.0 * log(2.0));
        d_gw[n] = (float)exp(-ax * ax / (2.0 * sig * sig));
        if (n < 3) d_acc[n] = 0.0;
    }
}

__global__ void k_siren1(const float* __restrict__ mg, const float* __restrict__ W1,
                         const float* __restrict__ b1, int M){
    int p = blockIdx.x; int o = threadIdx.x;
    if (p >= M) return;
    float x0 = mg[2*p], x1 = mg[2*p+1];
    float pre = x0 * W1[o] + x1 * W1[128 + o] + b1[o];
    d_hA[(size_t)p*128 + o] = sinf(30.f * pre);
}

// hidden layer as tiled SGEMM: 64 points x 128 outputs per block, 256 threads,
// 4x8 register tile per thread. Inner product in packed fma.rn.f32x2; the W
// operand is loaded DIRECTLY as u64 pairs from smem (no mov.b64 packing).
__global__ __launch_bounds__(256) void k_mid(const float* __restrict__ W,
                                             const float* __restrict__ b,
                                             int M, int dir){
    __shared__ __align__(16) float As[64][KC + 4];  // [p][k], row = 144B
    __shared__ __align__(16) float Ws[KC][128];     // [k][o], row = 512B
    const float* src = dir ? d_hB : d_hA;
    float*       dst = dir ? d_hA : d_hB;
    int p0  = blockIdx.x * 64;
    int tid = threadIdx.x;
    int tx  = tid & 15, ty = tid >> 4;
    unsigned long long acc2[4][4];
    const unsigned long long z2 = 0ull;   // (0.f, 0.f)
    #pragma unroll
    for (int u = 0; u < 4; u++)
        #pragma unroll
        for (int v = 0; v < 4; v++) acc2[u][v] = z2;

    for (int kc = 0; kc < 128; kc += KC){
        // A tile: 64 points x KC k-values = 512 float4 loads, 2 per thread
        #pragma unroll
        for (int q = 0; q < 2; q++){
            int f  = q*256 + tid;
            int p  = f >> 3;           // 8 float4 per point (KC/4 = 8)
            int kq = f & 7;
            float4 v = make_float4(0.f, 0.f, 0.f, 0.f);
            if (p0 + p < M)
                v = *reinterpret_cast<const float4*>(&src[(size_t)(p0+p)*128 + kc + kq*4]);
            *reinterpret_cast<float4*>(&As[p][kq*4]) = v;
        }
        // W tile: KC rows x 128 outputs = 1024 float4 loads, 4 per thread
        #pragma unroll
        for (int q = 0; q < 4; q++){
            int f  = q*256 + tid;
            int kr = f >> 5;
            int oq = f & 31;
            *reinterpret_cast<float4*>(&Ws[kr][oq*4]) =
                *reinterpret_cast<const float4*>(&W[(size_t)(kc+kr)*128 + oq*4]);
        }
        __syncthreads();
        #pragma unroll
        for (int k4 = 0; k4 < KC/4; k4++){
            float4 av[4];
            #pragma unroll
            for (int u = 0; u < 4; u++)
                av[u] = *reinterpret_cast<const float4*>(&As[ty*4 + u][k4*4]);
            #pragma unroll
            for (int kk = 0; kk < 4; kk++){
                int k = k4*4 + kk;
                const unsigned long long* wp0 =
                    reinterpret_cast<const unsigned long long*>(&Ws[k][tx*4]);
                const unsigned long long* wp1 =
                    reinterpret_cast<const unsigned long long*>(&Ws[k][64 + tx*4]);
                unsigned long long w2[4] = { wp0[0], wp0[1], wp1[0], wp1[1] };
                #pragma unroll
                for (int u = 0; u < 4; u++){
                    float aa = reinterpret_cast<const float*>(&av[u])[kk];
                    unsigned long long aa2 = pk2(aa, aa);
                    #pragma unroll
                    for (int v = 0; v < 4; v++) acc2[u][v] = fma2(aa2, w2[v], acc2[u][v]);
                }
            }
        }
        __syncthreads();
    }
    // epilogue: unpack, add bias, sin, store
    float bo[8];
    #pragma unroll
    for (int v = 0; v < 4; v++){
        bo[v]     = b[tx*4 + v];
        bo[v + 4] = b[64 + tx*4 + v];
    }
    #pragma unroll
    for (int u = 0; u < 4; u++){
        int p = p0 + ty*4 + u;
        if (p < M){
            float a[8];
            upk2(acc2[u][0], a[0], a[1]);
            upk2(acc2[u][1], a[2], a[3]);
            upk2(acc2[u][2], a[4], a[5]);
            upk2(acc2[u][3], a[6], a[7]);
            float4 r0, r1;
            r0.x = sinf(30.f*(a[0] + bo[0]));
            r0.y = sinf(30.f*(a[1] + bo[1]));
            r0.z = sinf(30.f*(a[2] + bo[2]));
            r0.w = sinf(30.f*(a[3] + bo[3]));
            r1.x = sinf(30.f*(a[4] + bo[4]));
            r1.y = sinf(30.f*(a[5] + bo[5]));
            r1.z = sinf(30.f*(a[6] + bo[6]));
            r1.w = sinf(30.f*(a[7] + bo[7]));
            *reinterpret_cast<float4*>(&dst[(size_t)p*128 + tx*4])      = r0;
            *reinterpret_cast<float4*>(&dst[(size_t)p*128 + 64 + tx*4]) = r1;
        }
    }
}

__global__ void k_siren_out(const float* __restrict__ W4, const float* __restrict__ b4,
                            const int* __restrict__ mask_idx, int M){
    int p    = blockIdx.x * 4 + (threadIdx.x >> 5);
    int lane = threadIdx.x & 31;
    if (p >= M) return;
    float acc = 0.f;
    for (int k = lane; k < 128; k += 32) acc += d_hA[(size_t)p*128 + k] * W4[k];
    #pragma unroll
    for (int o = 16; o; o >>= 1) acc += __shfl_down_sync(0xffffffffu, acc, o);
    if (lane == 0) d_SoS[mask_idx[p]] = (acc + b4[0]) * 170.f + 1550.f;
}

__global__ void k_wavefront(const float* __restrict__ xq_, const float* __restrict__ yq_,
                            const float* __restrict__ x_vec, const float* __restrict__ y_vec){
    int it = blockIdx.x;
    int j  = threadIdx.x;
    float xq = xq_[0], yq = yq_[0];
    float th  = (float)((double)it * (TWO_PI_D / 239.0));
    float r   = sqrtf(xq*xq + yq*yq);
    float phi = atan2f(xq, yq);
    float s   = sinf(th - phi), cd = cosf(th - phi);
    float rs  = r * s;
    float disc = 6.4e-5f - rs*rs; if (disc < 0.f) disc = 0.f;
    float sq = sqrtf(disc);
    float l  = (r < 0.008f) ? (sq + r*cd) : (2.f * sq * ((cd >= 0.f) ? 1.f : 0.f));
    float x0 = x_vec[0], dxv = x_vec[1] - x_vec[0];
    float y0 = y_vec[0], dyv = y_vec[1] - y_vec[0];
    float sth = sinf(th), cth = cosf(th);
    __shared__ float fint[NINT];
    __shared__ float xs[NINT];
    if (j < NINT){
        float step = (float)j / 249.0f;
        float xsj  = l * step;
        int xi = (int)rintf((xq - xsj*sth - x0) / dxv);
        int yi = (int)rintf((yq - xsj*cth - y0) / dyv);
        int ry = (((-yi) % 512) + 512) % 512;
        int rx = (((xi) % 512) + 512) % 512;
        fint[j] = 1.0f - 1500.0f / d_SoS[ry*512 + rx];
        xs[j] = xsj;
    }
    __syncthreads();
    float term = 0.f;
    if (j < NINT - 1) term = 0.5f * (fint[j] + fint[j+1]) * (xs[j+1] - xs[j]);
    float tot = blockReduce(term);
    if (j == 0) d_wfs[it] = tot;
}

// Row FFT of ifftshift(pad(y*GWIN)): rows are REAL, so pack two nonzero rows
// as one complex FFT and unpack by conjugate symmetry. 128 row-pairs/image.
__global__ void k_fft_rows_Y(const float* __restrict__ y_img){
    __shared__ float2 s0[512];
    __shared__ float2 s1[512];
    __shared__ float2 stw[256];
    int b = blockIdx.x; int a = b >> 7; int q = b & 127;
    int r1 = 2*q, r2 = 2*q + 1;
    int i1 = (r1 < 128) ? r1 : r1 + 256;       // nonzero output rows
    int i2 = (r2 < 128) ? r2 : r2 + 256;
    int lane = threadIdx.x;
    stw[lane]       = d_tw[lane];
    stw[lane + 128] = d_tw[lane + 128];
    int si1 = (i1 + 256) & 511;                // in [128,384)
    int si2 = (i2 + 256) & 511;
    float gy1 = d_gw[si1 - 128];
    float gy2 = d_gw[si2 - 128];
    const float* row1 = y_img + (size_t)a*65536 + (si1-128)*256;
    const float* row2 = y_img + (size_t)a*65536 + (si2-128)*256;
    for (int j = lane; j < 512; j += 128){
        int sj = (j + 256) & 511;
        float v1 = 0.f, v2 = 0.f;
        if (sj >= 128 && sj < 384){
            float gx = d_gw[sj - 128];
            v1 = row1[sj-128] * (gy1 * gx);
            v2 = row2[sj-128] * (gy2 * gx);
        }
        s0[j] = make_float2(v1, v2);           // z = row1 + i*row2
    }
    float2* res = fft512t(s0, s1, stw, lane, false);
    float2* o1 = &d_Y[((size_t)a*512 + i1) * 512];
    float2* o2 = &d_Y[((size_t)a*512 + i2) * 512];
    for (int j = lane; j < 512; j += 128){
        float2 zj = res[j];
        float2 zm = res[(512 - j) & 511];
        o1[j] = make_float2(0.5f*(zj.x + zm.x), 0.5f*(zj.y - zm.y));
        o2[j] = make_float2(0.5f*(zj.y + zm.y), 0.5f*(zm.x - zj.x));
    }
}

// Column FFT; input rows 128..383 known-zero (never written) -> synthesize zeros.
// Stores only rows 0..256 (k_solve reads only those; Nyquist-col extras use
// Y-index-Hermitian symmetry against rows 1..255).
__global__ void k_fft_cols_Y(){
    __shared__ float2 s0[4][514];
    __shared__ float2 s1[4][514];
    __shared__ float2 stw[256];
    int blk = blockIdx.x; int a = blk >> 7; int j0 = (blk & 127) << 2;
    int tx = threadIdx.x, ty = threadIdx.y;
    int ltid = tx + ty * 4;
    if (ltid < 256) stw[ltid] = d_tw[ltid];
    float2* base = &d_Y[(size_t)a * NPIX];
    s0[tx][ty]       = base[ty*512 + j0 + tx];
    s0[tx][ty + 128] = make_float2(0.f, 0.f);
    s0[tx][ty + 256] = make_float2(0.f, 0.f);
    s0[tx][ty + 384] = base[(ty + 384)*512 + j0 + tx];
    float2* res = fft512t(&s0[tx][0], &s1[tx][0], stw, ty, false);
    #pragma unroll
    for (int rr = 0; rr < 3; rr++){
        int i = ty + rr*128;
        if (i <= 256) base[i*512 + j0 + tx] = res[i];
    }
}

// Fused: H on the fly + Wiener solve + data loss on the Hermitian half-plane,
// with EXACT Nyquist handling:
//  - rows 1..255, j != 256: weight 2, conj-mirror write to (512-i, (512-j)&511)
//  - rows 1..255, j == 256: weight 1, NO mirror (H not index-Hermitian at col 256)
//  - row 0: within-row mirror valid (fi=0); j in 1..255 weight 2, j=0/256 weight 1
//  - row 256 (Nyquist): ALL j computed directly, weight 1, no mirror
//  - extra block: pixels (r, 256), r=257..511 computed directly (weight 1),
//    reading Y[r][256] = conj(Y[512-r][256]) (exact DFT identity).
__global__ void k_solve(const float* __restrict__ delays){
    __shared__ float swf[NTH];
    __shared__ float sd[ND];
    int t = threadIdx.x;
    if (t < NTH) swf[t] = d_wfs[t];
    if (t < ND)  sd[t]  = delays[t];
    __syncthreads();
    int i = 0, j = 0;
    bool yconj = false, valid = true;
    int mirror = 0;                 // 0 none, 1 row0-within, 2 full
    float wgt = 0.f;
    if (blockIdx.x < 514){
        int p = blockIdx.x * 256 + t;          // p < 257*512
        i = p >> 9; j = p & 511;
        if (i == 256){
            wgt = 1.f;                          // Nyquist row: direct, all j
        } else if (i == 0){
            wgt = (j == 0 || j == 256) ? 1.f : (j < 256 ? 2.f : 0.f);
            if (j >= 1 && j <= 255) mirror = 1;
        } else {
            if (j == 256){ wgt = 1.f; }        // Nyquist col: direct, no mirror
            else { wgt = 2.f; mirror = 2; }
        }
        if (wgt == 0.f) valid = false;
    } else {
        // extra block: (r, 256) for r = 257..511
        if (t < 255){ i = 257 + t; j = 256; yconj = true; wgt = 1.f; }
        else valid = false;
    }
    float loc = 0.f;
    if (valid){
        float fi = (float)(i < 256 ? i : i - 512) * 48.828125f;
        float fj = (float)(j < 256 ? j : j - 512) * 48.828125f;
        float kk = TWO_PI_F * sqrtf(fi*fi + fj*fj);
        float th = atan2f(fj, fi);
        if (th < 0.f) th += TWO_PI_F;
        float w  = interp_wf(th, swf);
        float tp = th + PI_F;
        tp = tp - floorf(tp / TWO_PI_F) * TWO_PI_F;
        float wpi = interp_wf(tp, swf);
        float C = 0.5f * kk * (w + wpi);
        float S = 0.5f * kk * (w - wpi);
        float sS, cS; __sincosf(S, &sS, &cS);
        int ysrc = yconj ? ((512 - i)*512 + 256) : (i*512 + j);
        float ysign = yconj ? -1.f : 1.f;
        float Syx = 0.f, Syy = 0.f, lhs = 0.f, sy2 = 0.f, syh = 0.f;
        #pragma unroll 4
        for (int a = 0; a < ND; a++){
            float c = __cosf(C - kk * sd[a]);      // h_a = c * e^{iS}
            float2 y = d_Y[(size_t)a*NPIX + ysrc];
            y.y *= ysign;
            Syx += y.x * c;
            Syy += y.y * c;
            float c2 = c * c;
            lhs += c2;
            float ay2 = y.x*y.x + y.y*y.y;
            sy2 += ay2;
            syh += sqrtf(ay2 * c2);                // |y_a| * |h_a|
        }
        float inv = 1.f / lhs;
        // X = conj(e^{iS}) * Sy / lhs
        float xr = (Syx*cS + Syy*sS) * inv;
        float xi = (Syy*cS - Syx*sS) * inv;
        d_Xf[i*512 + j] = make_float2(xr, xi);
        if (mirror == 2){
            d_Xf[(512 - i)*512 + ((512 - j) & 511)] = make_float2(xr, -xi);
        } else if (mirror == 1){
            d_Xf[512 - j] = make_float2(xr, -xi);  // row 0, cols 257..511
        }
        float xm = sqrtf(xr*xr + xi*xi);
        loc = wgt * kk*kk * (sy2 - 2.f*xm*syh + xm*xm*lhs);
    }
    float tot = blockReduce(loc);
    if (t == 0) atomicAdd(&d_acc[0], (double)tot);
}

__global__ void k_ifft_rows(){
    __shared__ float2 s0[512];
    __shared__ float2 s1[512];
    __shared__ float2 stw[256];
    int i = blockIdx.x; int lane = threadIdx.x;
    stw[lane]       = d_tw[lane];
    stw[lane + 128] = d_tw[lane + 128];
    for (int j = lane; j < 512; j += 128) s0[j] = d_Xf[i*512 + j];
    float2* res = fft512t(s0, s1, stw, lane, true);
    const float sc = 1.f / 512.f;
    for (int j = lane; j < 512; j += 128){
        float2 v = res[j];
        d_T[i*512 + j] = make_float2(v.x * sc, v.y * sc);
    }
}

// inverse FFT columns + fftshift + real -> x_rec directly into d_out
__global__ void k_ifft_cols_out(float* __restrict__ out){
    __shared__ float2 s0[4][514];
    __shared__ float2 s1[4][514];
    __shared__ float2 stw[256];
    int j0 = (blockIdx.x & 127) << 2;
    int tx = threadIdx.x, ty = threadIdx.y;
    int ltid = tx + ty * 4;
    if (ltid < 256) stw[ltid] = d_tw[ltid];
    #pragma unroll
    for (int rr = 0; rr < 4; rr++){
        int i = ty + rr*128;
        s0[tx][i] = d_T[i*512 + j0 + tx];
    }
    float2* res = fft512t(&s0[tx][0], &s1[tx][0], stw, ty, true);
    const float sc = 1.f / 512.f;
    int oj = ((j0 + tx) + 256) & 511;
    #pragma unroll
    for (int rr = 0; rr < 4; rr++){
        int i = ty + rr*128;
        int oi = (i + 256) & 511;
        out[oi*512 + oj] = res[i].x * sc;
    }
}

__global__ void k_tv_l1(const float* __restrict__ mask, float* __restrict__ out){
    int p = blockIdx.x * 256 + threadIdx.x;
    int i = p >> 9, j = p & 511;
    float S = d_SoS[p];
    out[NPIX + p] = S;                      // SoS copy fused here
    float m = mask[p];
    float tv = 0.f;
    if (i > 0) tv += fabsf((S - d_SoS[p - 512]) * m);
    if (j > 0) tv += fabsf((S - d_SoS[p - 1]) * m);
    float l1 = fabsf(S - 1550.f) * m;
    float t1 = blockReduce(tv);
    if (threadIdx.x == 0) atomicAdd(&d_acc[1], (double)t1);
    float t2 = blockReduce(l1);
    if (threadIdx.x == 0) atomicAdd(&d_acc[2], (double)t2);
}

__global__ void k_final(float* __restrict__ out){
    double data = d_acc[0] / (double)((size_t)ND * NPIX);
    double loss = data + 0.001 * d_acc[1] + 0.001 * (d_acc[2] / (double)NPIX);
    out[2 * NPIX] = (float)loss;
}

// ---------------- launch ----------------
extern "C" void kernel_launch(void* const* d_in, const int* in_sizes, int n_in,
                              void* d_out, int out_size){
    const float* W1  = (const float*)d_in[0];
    const float* b1  = (const float*)d_in[1];
    const float* W2  = (const float*)d_in[2];
    const float* b2  = (const float*)d_in[3];
    const float* W3  = (const float*)d_in[4];
    const float* b3  = (const float*)d_in[5];
    const float* W4  = (const float*)d_in[6];
    const float* b4  = (const float*)d_in[7];
    const float* y_img   = (const float*)d_in[8];
    const float* delays  = (const float*)d_in[9];
    const float* xq      = (const float*)d_in[10];
    const float* yq      = (const float*)d_in[11];
    const float* mgrid   = (const float*)d_in[12];
    const float* mask    = (const float*)d_in[13];
    const int*   mask_idx= (const int*)  d_in[14];
    const float* x_vec   = (const float*)d_in[15];
    const float* y_vec   = (const float*)d_in[16];
    int M = in_sizes[14];
    if (M > MAXM) M = MAXM;
    float* out = (float*)d_out;

    k_prep<<<NPIX/256, 256>>>();

    // SIREN
    k_siren1<<<M, 128>>>(mgrid, W1, b1, M);
    k_mid<<<(M + 63) / 64, 256>>>(W2, b2, M, 0);     // hA -> hB
    k_mid<<<(M + 63) / 64, 256>>>(W3, b3, M, 1);     // hB -> hA
    k_siren_out<<<(M + 3) / 4, 128>>>(W4, b4, mask_idx, M);

    // wavefront
    k_wavefront<<<NTH, 256>>>(xq, yq, x_vec, y_vec);

    // Y = fft2(ifftshift(pad(y*GWIN)))  (zero rows skipped, real rows packed,
    // only rows 0..256 stored)
    k_fft_rows_Y<<<ND*128, 128>>>(y_img);
    k_fft_cols_Y<<<ND*128, dim3(4, 128)>>>();

    // fused H + Wiener solve + data loss (half-plane + exact Nyquist handling)
    k_solve<<<515, 256>>>(delays);

    // reconstruction (unmodified full-plane)
    k_ifft_rows<<<512, 128>>>();
    k_ifft_cols_out<<<128, dim3(4, 128)>>>(out);

    // losses + SoS copy
    k_tv_l1<<<NPIX/256, 256>>>(mask, out);
    k_final<<<1, 1>>>(out);
}

// round 14
// speedup vs baseline: 1.4860x; 1.4860x over previous
#include <cuda_runtime.h>
#include <math.h>

#define NPAD  512
#define NPIX  (512*512)
#define ND    32
#define NTH   240
#define NINT  250
#define NIMG  256
#define MAXM  40960
#define KC    32
#define PI_F      3.14159265358979323846f
#define TWO_PI_F  6.28318530717958647692f
#define TWO_PI_D  6.283185307179586476925286766559

// ---------------- scratch (static device globals; no allocations) ----------
__device__ float2 d_Y[(size_t)ND*NPIX];   // FFT of padded windowed images
__device__ float2 d_Xf[NPIX];             // Wiener solution in freq domain
__device__ float2 d_T[NPIX];              // ifft intermediate
__device__ float  d_SoS[NPIX];
__device__ float  d_hA[(size_t)MAXM*128];
__device__ float  d_hB[(size_t)MAXM*128];
__device__ float  d_wfs[NTH];
__device__ float2 d_tw[256];              // e^{-i pi n / 256}
__device__ float  d_gw[256];              // Gaussian window 1D factors
__device__ double d_acc[3];               // data, tv, l1 accumulators

// ---------------- helpers ----------------
__device__ __forceinline__ float blockReduce(float v){
    __shared__ float red[32];
    int lane = threadIdx.x & 31, w = threadIdx.x >> 5;
    #pragma unroll
    for (int o = 16; o; o >>= 1) v += __shfl_down_sync(0xffffffffu, v, o);
    __syncthreads();
    if (lane == 0) red[w] = v;
    __syncthreads();
    float r = 0.f;
    if (w == 0){
        int nw = (blockDim.x + 31) >> 5;
        r = (lane < nw) ? red[lane] : 0.f;
        #pragma unroll
        for (int o = 16; o; o >>= 1) r += __shfl_down_sync(0xffffffffu, r, o);
    }
    __syncthreads();
    return r;  // valid on thread 0
}

// packed fp32x2 helpers (Blackwell f32x2 pipe; per-lane .rn rounding)
__device__ __forceinline__ unsigned long long pk2(float lo, float hi){
    unsigned long long r;
    asm("mov.b64 %0, {%1, %2};" : "=l"(r) : "f"(lo), "f"(hi));
    return r;
}
__device__ __forceinline__ unsigned long long fma2(unsigned long long a,
                                                   unsigned long long b,
                                                   unsigned long long c){
    unsigned long long d;
    asm("fma.rn.f32x2 %0, %1, %2, %3;" : "=l"(d) : "l"(a), "l"(b), "l"(c));
    return d;
}
__device__ __forceinline__ void upk2(unsigned long long v, float& lo, float& hi){
    asm("mov.b64 {%0, %1}, %2;" : "=f"(lo), "=f"(hi) : "l"(v));
}

// 1D interpolation over the 240-point theta grid (matches reference _interp1d)
__device__ __forceinline__ float interp_wf(float xn, const float* wf){
    const double step = TWO_PI_D / 239.0;
    const float dxg = (float)step;
    float t = xn / dxg;
    int fi = (int)floorf(t); fi = fi < 0 ? 0 : (fi > 239 ? 239 : fi);
    int ci = (int)ceilf(t);  ci = ci < 0 ? 0 : (ci > 239 ? 239 : ci);
    float yc = wf[ci];
    if (ci == fi) return yc;
    float yf = wf[fi];
    float xf = (float)((double)fi * step);
    float xc = (float)((double)ci * step);
    return yf + (yc - yf) * (xn - xf) / (xc - xf);
}

// Stockham radix-2 512-point FFT with shared twiddle table. 128 lanes/line.
__device__ __forceinline__ float2* fft512t(float2* a, float2* b,
                                           const float2* tw, int lane, bool inv){
    float2* src = a; float2* dst = b;
    #pragma unroll
    for (int s = 0; s < 9; s++){
        int m = 1 << s;
        __syncthreads();
        #pragma unroll
        for (int h = 0; h < 2; h++){
            int t = lane + h * 128;          // butterfly index 0..255
            int j = t >> s;
            int k = t & (m - 1);
            float2 c0 = src[j*m + k];
            float2 c1 = src[j*m + k + 256];
            float2 w = tw[t & ~(m - 1)];     // e^{-i pi (j<<s) / 256}
            float wy = inv ? -w.y : w.y;
            float dx = c0.x - c1.x, dy = c0.y - c1.y;
            dst[2*j*m + k]     = make_float2(c0.x + c1.x, c0.y + c1.y);
            dst[2*j*m + m + k] = make_float2(w.x*dx - wy*dy, w.x*dy + wy*dx);
        }
        float2* tmp = src; src = dst; dst = tmp;
    }
    __syncthreads();
    return src;
}

// ---------------- kernels ----------------
// SoS fill + (block 0) twiddle/window/accumulator init
__global__ void k_prep(){
    int p = blockIdx.x * 256 + threadIdx.x;
    d_SoS[p] = 1499.363f;
    if (blockIdx.x == 0){
        int n = threadIdx.x;
        float s, c;
        sincosf(PI_F * (float)n / 256.f, &s, &c);
        d_tw[n] = make_float2(c, -s);
        double ax  = (double)n - 127.5;
        double sig = 37.5 / sqrt(2.0 * log(2.0));
        d_gw[n] = (float)exp(-ax * ax / (2.0 * sig * sig));
        if (n < 3) d_acc[n] = 0.0;
    }
}

__global__ void k_siren1(const float* __restrict__ mg, const float* __restrict__ W1,
                         const float* __restrict__ b1, int M){
    int p = blockIdx.x; int o = threadIdx.x;
    if (p >= M) return;
    float x0 = mg[2*p], x1 = mg[2*p+1];
    float pre = x0 * W1[o] + x1 * W1[128 + o] + b1[o];
    d_hA[(size_t)p*128 + o] = sinf(30.f * pre);
}

// hidden layer as tiled SGEMM: 64 points x 128 outputs per block, 256 threads,
// 4x8 register tile per thread. Inner product in packed fma.rn.f32x2; the W
// operand is loaded DIRECTLY as u64 pairs from smem (no mov.b64 packing).
__global__ __launch_bounds__(256) void k_mid(const float* __restrict__ W,
                                             const float* __restrict__ b,
                                             int M, int dir){
    __shared__ __align__(16) float As[64][KC + 4];  // [p][k], row = 144B
    __shared__ __align__(16) float Ws[KC][128];     // [k][o], row = 512B
    const float* src = dir ? d_hB : d_hA;
    float*       dst = dir ? d_hA : d_hB;
    int p0  = blockIdx.x * 64;
    int tid = threadIdx.x;
    int tx  = tid & 15, ty = tid >> 4;
    unsigned long long acc2[4][4];
    const unsigned long long z2 = 0ull;   // (0.f, 0.f)
    #pragma unroll
    for (int u = 0; u < 4; u++)
        #pragma unroll
        for (int v = 0; v < 4; v++) acc2[u][v] = z2;

    for (int kc = 0; kc < 128; kc += KC){
        // A tile: 64 points x KC k-values = 512 float4 loads, 2 per thread
        #pragma unroll
        for (int q = 0; q < 2; q++){
            int f  = q*256 + tid;
            int p  = f >> 3;           // 8 float4 per point (KC/4 = 8)
            int kq = f & 7;
            float4 v = make_float4(0.f, 0.f, 0.f, 0.f);
            if (p0 + p < M)
                v = *reinterpret_cast<const float4*>(&src[(size_t)(p0+p)*128 + kc + kq*4]);
            *reinterpret_cast<float4*>(&As[p][kq*4]) = v;
        }
        // W tile: KC rows x 128 outputs = 1024 float4 loads, 4 per thread
        #pragma unroll
        for (int q = 0; q < 4; q++){
            int f  = q*256 + tid;
            int kr = f >> 5;
            int oq = f & 31;
            *reinterpret_cast<float4*>(&Ws[kr][oq*4]) =
                *reinterpret_cast<const float4*>(&W[(size_t)(kc+kr)*128 + oq*4]);
        }
        __syncthreads();
        #pragma unroll
        for (int k4 = 0; k4 < KC/4; k4++){
            float4 av[4];
            #pragma unroll
            for (int u = 0; u < 4; u++)
                av[u] = *reinterpret_cast<const float4*>(&As[ty*4 + u][k4*4]);
            #pragma unroll
            for (int kk = 0; kk < 4; kk++){
                int k = k4*4 + kk;
                const unsigned long long* wp0 =
                    reinterpret_cast<const unsigned long long*>(&Ws[k][tx*4]);
                const unsigned long long* wp1 =
                    reinterpret_cast<const unsigned long long*>(&Ws[k][64 + tx*4]);
                unsigned long long w2[4] = { wp0[0], wp0[1], wp1[0], wp1[1] };
                #pragma unroll
                for (int u = 0; u < 4; u++){
                    float aa = reinterpret_cast<const float*>(&av[u])[kk];
                    unsigned long long aa2 = pk2(aa, aa);
                    #pragma unroll
                    for (int v = 0; v < 4; v++) acc2[u][v] = fma2(aa2, w2[v], acc2[u][v]);
                }
            }
        }
        __syncthreads();
    }
    // epilogue: unpack, add bias, sin, store
    float bo[8];
    #pragma unroll
    for (int v = 0; v < 4; v++){
        bo[v]     = b[tx*4 + v];
        bo[v + 4] = b[64 + tx*4 + v];
    }
    #pragma unroll
    for (int u = 0; u < 4; u++){
        int p = p0 + ty*4 + u;
        if (p < M){
            float a[8];
            upk2(acc2[u][0], a[0], a[1]);
            upk2(acc2[u][1], a[2], a[3]);
            upk2(acc2[u][2], a[4], a[5]);
            upk2(acc2[u][3], a[6], a[7]);
            float4 r0, r1;
            r0.x = sinf(30.f*(a[0] + bo[0]));
            r0.y = sinf(30.f*(a[1] + bo[1]));
            r0.z = sinf(30.f*(a[2] + bo[2]));
            r0.w = sinf(30.f*(a[3] + bo[3]));
            r1.x = sinf(30.f*(a[4] + bo[4]));
            r1.y = sinf(30.f*(a[5] + bo[5]));
            r1.z = sinf(30.f*(a[6] + bo[6]));
            r1.w = sinf(30.f*(a[7] + bo[7]));
            *reinterpret_cast<float4*>(&dst[(size_t)p*128 + tx*4])      = r0;
            *reinterpret_cast<float4*>(&dst[(size_t)p*128 + 64 + tx*4]) = r1;
        }
    }
}

__global__ void k_siren_out(const float* __restrict__ W4, const float* __restrict__ b4,
                            const int* __restrict__ mask_idx, int M){
    int p    = blockIdx.x * 4 + (threadIdx.x >> 5);
    int lane = threadIdx.x & 31;
    if (p >= M) return;
    float acc = 0.f;
    for (int k = lane; k < 128; k += 32) acc += d_hA[(size_t)p*128 + k] * W4[k];
    #pragma unroll
    for (int o = 16; o; o >>= 1) acc += __shfl_down_sync(0xffffffffu, acc, o);
    if (lane == 0) d_SoS[mask_idx[p]] = (acc + b4[0]) * 170.f + 1550.f;
}

__global__ void k_wavefront(const float* __restrict__ xq_, const float* __restrict__ yq_,
                            const float* __restrict__ x_vec, const float* __restrict__ y_vec){
    int it = blockIdx.x;
    int j  = threadIdx.x;
    float xq = xq_[0], yq = yq_[0];
    float th  = (float)((double)it * (TWO_PI_D / 239.0));
    float r   = sqrtf(xq*xq + yq*yq);
    float phi = atan2f(xq, yq);
    float s   = sinf(th - phi), cd = cosf(th - phi);
    float rs  = r * s;
    float disc = 6.4e-5f - rs*rs; if (disc < 0.f) disc = 0.f;
    float sq = sqrtf(disc);
    float l  = (r < 0.008f) ? (sq + r*cd) : (2.f * sq * ((cd >= 0.f) ? 1.f : 0.f));
    float x0 = x_vec[0], dxv = x_vec[1] - x_vec[0];
    float y0 = y_vec[0], dyv = y_vec[1] - y_vec[0];
    float sth = sinf(th), cth = cosf(th);
    __shared__ float fint[NINT];
    __shared__ float xs[NINT];
    if (j < NINT){
        float step = (float)j / 249.0f;
        float xsj  = l * step;
        int xi = (int)rintf((xq - xsj*sth - x0) / dxv);
        int yi = (int)rintf((yq - xsj*cth - y0) / dyv);
        int ry = (((-yi) % 512) + 512) % 512;
        int rx = (((xi) % 512) + 512) % 512;
        fint[j] = 1.0f - 1500.0f / d_SoS[ry*512 + rx];
        xs[j] = xsj;
    }
    __syncthreads();
    float term = 0.f;
    if (j < NINT - 1) term = 0.5f * (fint[j] + fint[j+1]) * (xs[j+1] - xs[j]);
    float tot = blockReduce(term);
    if (j == 0) d_wfs[it] = tot;
}

// Row FFT of ifftshift(pad(y*GWIN)): rows are REAL, so pack two nonzero rows
// as one complex FFT and unpack by conjugate symmetry. 128 row-pairs/image.
__global__ void k_fft_rows_Y(const float* __restrict__ y_img){
    __shared__ float2 s0[512];
    __shared__ float2 s1[512];
    __shared__ float2 stw[256];
    int b = blockIdx.x; int a = b >> 7; int q = b & 127;
    int r1 = 2*q, r2 = 2*q + 1;
    int i1 = (r1 < 128) ? r1 : r1 + 256;       // nonzero output rows
    int i2 = (r2 < 128) ? r2 : r2 + 256;
    int lane = threadIdx.x;
    stw[lane]       = d_tw[lane];
    stw[lane + 128] = d_tw[lane + 128];
    int si1 = (i1 + 256) & 511;                // in [128,384)
    int si2 = (i2 + 256) & 511;
    float gy1 = d_gw[si1 - 128];
    float gy2 = d_gw[si2 - 128];
    const float* row1 = y_img + (size_t)a*65536 + (si1-128)*256;
    const float* row2 = y_img + (size_t)a*65536 + (si2-128)*256;
    for (int j = lane; j < 512; j += 128){
        int sj = (j + 256) & 511;
        float v1 = 0.f, v2 = 0.f;
        if (sj >= 128 && sj < 384){
            float gx = d_gw[sj - 128];
            v1 = row1[sj-128] * (gy1 * gx);
            v2 = row2[sj-128] * (gy2 * gx);
        }
        s0[j] = make_float2(v1, v2);           // z = row1 + i*row2
    }
    float2* res = fft512t(s0, s1, stw, lane, false);
    float2* o1 = &d_Y[((size_t)a*512 + i1) * 512];
    float2* o2 = &d_Y[((size_t)a*512 + i2) * 512];
    for (int j = lane; j < 512; j += 128){
        float2 zj = res[j];
        float2 zm = res[(512 - j) & 511];
        o1[j] = make_float2(0.5f*(zj.x + zm.x), 0.5f*(zj.y - zm.y));
        o2[j] = make_float2(0.5f*(zj.y + zm.y), 0.5f*(zm.x - zj.x));
    }
}

// Column FFT; input rows 128..383 known-zero (never written) -> synthesize zeros.
// Stores only rows 0..256 (k_solve reads only those; Nyquist-col extras use
// Y-index-Hermitian symmetry against rows 1..255).
__global__ void k_fft_cols_Y(){
    __shared__ float2 s0[4][514];
    __shared__ float2 s1[4][514];
    __shared__ float2 stw[256];
    int blk = blockIdx.x; int a = blk >> 7; int j0 = (blk & 127) << 2;
    int tx = threadIdx.x, ty = threadIdx.y;
    int ltid = tx + ty * 4;
    if (ltid < 256) stw[ltid] = d_tw[ltid];
    float2* base = &d_Y[(size_t)a * NPIX];
    s0[tx][ty]       = base[ty*512 + j0 + tx];
    s0[tx][ty + 128] = make_float2(0.f, 0.f);
    s0[tx][ty + 256] = make_float2(0.f, 0.f);
    s0[tx][ty + 384] = base[(ty + 384)*512 + j0 + tx];
    float2* res = fft512t(&s0[tx][0], &s1[tx][0], stw, ty, false);
    #pragma unroll
    for (int rr = 0; rr < 3; rr++){
        int i = ty + rr*128;
        if (i <= 256) base[i*512 + j0 + tx] = res[i];
    }
}

// Fused: H on the fly + Wiener solve + data loss on the Hermitian half-plane,
// with EXACT Nyquist handling:
//  - rows 1..255, j != 256: weight 2, conj-mirror write to (512-i, (512-j)&511)
//  - rows 1..255, j == 256: weight 1, NO mirror (H not index-Hermitian at col 256)
//  - row 0: within-row mirror valid (fi=0); j in 1..255 weight 2, j=0/256 weight 1
//  - row 256 (Nyquist): ALL j computed directly, weight 1, no mirror
//  - extra block: pixels (r, 256), r=257..511 computed directly (weight 1),
//    reading Y[r][256] = conj(Y[512-r][256]) (exact DFT identity).
__global__ void k_solve(const float* __restrict__ delays){
    __shared__ float swf[NTH];
    __shared__ float sd[ND];
    int t = threadIdx.x;
    if (t < NTH) swf[t] = d_wfs[t];
    if (t < ND)  sd[t]  = delays[t];
    __syncthreads();
    int i = 0, j = 0;
    bool yconj = false, valid = true;
    int mirror = 0;                 // 0 none, 1 row0-within, 2 full
    float wgt = 0.f;
    if (blockIdx.x < 514){
        int p = blockIdx.x * 256 + t;          // p < 257*512
        i = p >> 9; j = p & 511;
        if (i == 256){
            wgt = 1.f;                          // Nyquist row: direct, all j
        } else if (i == 0){
            wgt = (j == 0 || j == 256) ? 1.f : (j < 256 ? 2.f : 0.f);
            if (j >= 1 && j <= 255) mirror = 1;
        } else {
            if (j == 256){ wgt = 1.f; }        // Nyquist col: direct, no mirror
            else { wgt = 2.f; mirror = 2; }
        }
        if (wgt == 0.f) valid = false;
    } else {
        // extra block: (r, 256) for r = 257..511
        if (t < 255){ i = 257 + t; j = 256; yconj = true; wgt = 1.f; }
        else valid = false;
    }
    float loc = 0.f;
    if (valid){
        float fi = (float)(i < 256 ? i : i - 512) * 48.828125f;
        float fj = (float)(j < 256 ? j : j - 512) * 48.828125f;
        float kk = TWO_PI_F * sqrtf(fi*fi + fj*fj);
        float th = atan2f(fj, fi);
        if (th < 0.f) th += TWO_PI_F;
        float w  = interp_wf(th, swf);
        float tp = th + PI_F;
        tp = tp - floorf(tp / TWO_PI_F) * TWO_PI_F;
        float wpi = interp_wf(tp, swf);
        float C = 0.5f * kk * (w + wpi);
        float S = 0.5f * kk * (w - wpi);
        float sS, cS; __sincosf(S, &sS, &cS);
        int ysrc = yconj ? ((512 - i)*512 + 256) : (i*512 + j);
        float ysign = yconj ? -1.f : 1.f;
        float Syx = 0.f, Syy = 0.f, lhs = 0.f, sy2 = 0.f, syh = 0.f;
        #pragma unroll 4
        for (int a = 0; a < ND; a++){
            float c = __cosf(C - kk * sd[a]);      // h_a = c * e^{iS}
            float2 y = d_Y[(size_t)a*NPIX + ysrc];
            y.y *= ysign;
            Syx += y.x * c;
            Syy += y.y * c;
            float c2 = c * c;
            lhs += c2;
            float ay2 = y.x*y.x + y.y*y.y;
            sy2 += ay2;
            syh += sqrtf(ay2 * c2);                // |y_a| * |h_a|
        }
        float inv = 1.f / lhs;
        // X = conj(e^{iS}) * Sy / lhs
        float xr = (Syx*cS + Syy*sS) * inv;
        float xi = (Syy*cS - Syx*sS) * inv;
        d_Xf[i*512 + j] = make_float2(xr, xi);
        if (mirror == 2){
            d_Xf[(512 - i)*512 + ((512 - j) & 511)] = make_float2(xr, -xi);
        } else if (mirror == 1){
            d_Xf[512 - j] = make_float2(xr, -xi);  // row 0, cols 257..511
        }
        float xm = sqrtf(xr*xr + xi*xi);
        loc = wgt * kk*kk * (sy2 - 2.f*xm*syh + xm*xm*lhs);
    }
    float tot = blockReduce(loc);
    if (t == 0) atomicAdd(&d_acc[0], (double)tot);
}

__global__ void k_ifft_rows(){
    __shared__ float2 s0[512];
    __shared__ float2 s1[512];
    __shared__ float2 stw[256];
    int i = blockIdx.x; int lane = threadIdx.x;
    stw[lane]       = d_tw[lane];
    stw[lane + 128] = d_tw[lane + 128];
    for (int j = lane; j < 512; j += 128) s0[j] = d_Xf[i*512 + j];
    float2* res = fft512t(s0, s1, stw, lane, true);
    const float sc = 1.f / 512.f;
    for (int j = lane; j < 512; j += 128){
        float2 v = res[j];
        d_T[i*512 + j] = make_float2(v.x * sc, v.y * sc);
    }
}

// inverse FFT columns + fftshift + real -> x_rec directly into d_out
__global__ void k_ifft_cols_out(float* __restrict__ out){
    __shared__ float2 s0[4][514];
    __shared__ float2 s1[4][514];
    __shared__ float2 stw[256];
    int j0 = (blockIdx.x & 127) << 2;
    int tx = threadIdx.x, ty = threadIdx.y;
    int ltid = tx + ty * 4;
    if (ltid < 256) stw[ltid] = d_tw[ltid];
    #pragma unroll
    for (int rr = 0; rr < 4; rr++){
        int i = ty + rr*128;
        s0[tx][i] = d_T[i*512 + j0 + tx];
    }
    float2* res = fft512t(&s0[tx][0], &s1[tx][0], stw, ty, true);
    const float sc = 1.f / 512.f;
    int oj = ((j0 + tx) + 256) & 511;
    #pragma unroll
    for (int rr = 0; rr < 4; rr++){
        int i = ty + rr*128;
        int oi = (i + 256) & 511;
        out[oi*512 + oj] = res[i].x * sc;
    }
}

__global__ void k_tv_l1(const float* __restrict__ mask, float* __restrict__ out){
    int p = blockIdx.x * 256 + threadIdx.x;
    int i = p >> 9, j = p & 511;
    float S = d_SoS[p];
    out[NPIX + p] = S;                      // SoS copy fused here
    float m = mask[p];
    float tv = 0.f;
    if (i > 0) tv += fabsf((S - d_SoS[p - 512]) * m);
    if (j > 0) tv += fabsf((S - d_SoS[p - 1]) * m);
    float l1 = fabsf(S - 1550.f) * m;
    float t1 = blockReduce(tv);
    if (threadIdx.x == 0) atomicAdd(&d_acc[1], (double)t1);
    float t2 = blockReduce(l1);
    if (threadIdx.x == 0) atomicAdd(&d_acc[2], (double)t2);
}

__global__ void k_final(float* __restrict__ out){
    double data = d_acc[0] / (double)((size_t)ND * NPIX);
    double loss = data + 0.001 * d_acc[1] + 0.001 * (d_acc[2] / (double)NPIX);
    out[2 * NPIX] = (float)loss;
}

// ---------------- launch ----------------
extern "C" void kernel_launch(void* const* d_in, const int* in_sizes, int n_in,
                              void* d_out, int out_size){
    const float* W1  = (const float*)d_in[0];
    const float* b1  = (const float*)d_in[1];
    const float* W2  = (const float*)d_in[2];
    const float* b2  = (const float*)d_in[3];
    const float* W3  = (const float*)d_in[4];
    const float* b3  = (const float*)d_in[5];
    const float* W4  = (const float*)d_in[6];
    const float* b4  = (const float*)d_in[7];
    const float* y_img   = (const float*)d_in[8];
    const float* delays  = (const float*)d_in[9];
    const float* xq      = (const float*)d_in[10];
    const float* yq      = (const float*)d_in[11];
    const float* mgrid   = (const float*)d_in[12];
    const float* mask    = (const float*)d_in[13];
    const int*   mask_idx= (const int*)  d_in[14];
    const float* x_vec   = (const float*)d_in[15];
    const float* y_vec   = (const float*)d_in[16];
    int M = in_sizes[14];
    if (M > MAXM) M = MAXM;
    float* out = (float*)d_out;

    k_prep<<<NPIX/256, 256>>>();

    // SIREN
    k_siren1<<<M, 128>>>(mgrid, W1, b1, M);
    k_mid<<<(M + 63) / 64, 256>>>(W2, b2, M, 0);     // hA -> hB
    k_mid<<<(M + 63) / 64, 256>>>(W3, b3, M, 1);     // hB -> hA
    k_siren_out<<<(M + 3) / 4, 128>>>(W4, b4, mask_idx, M);

    // wavefront
    k_wavefront<<<NTH, 256>>>(xq, yq, x_vec, y_vec);

    // Y = fft2(ifftshift(pad(y*GWIN)))  (zero rows skipped, real rows packed,
    // only rows 0..256 stored)
    k_fft_rows_Y<<<ND*128, 128>>>(y_img);
    k_fft_cols_Y<<<ND*128, dim3(4, 128)>>>();

    // fused H + Wiener solve + data loss (half-plane + exact Nyquist handling)
    k_solve<<<515, 256>>>(delays);

    // reconstruction (unmodified full-plane)
    k_ifft_rows<<<512, 128>>>();
    k_ifft_cols_out<<<128, dim3(4, 128)>>>(out);

    // losses + SoS copy
    k_tv_l1<<<NPIX/256, 256>>>(mask, out);
    k_final<<<1, 1>>>(out);
}

// round 15
// speedup vs baseline: 1.6303x; 1.0971x over previous
#include <cuda_runtime.h>
#include <math.h>

#define NPAD  512
#define NPIX  (512*512)
#define ND    32
#define NTH   240
#define NINT  250
#define NIMG  256
#define MAXM  40960
#define KC    32
#define PI_F      3.14159265358979323846f
#define TWO_PI_F  6.28318530717958647692f
#define TWO_PI_D  6.283185307179586476925286766559

// ---------------- scratch (static device globals; no allocations) ----------
__device__ float2 d_Y[(size_t)ND*NPIX];   // FFT of padded windowed images
__device__ float2 d_Xf[NPIX];             // Wiener solution in freq domain
__device__ float2 d_T[NPIX];              // ifft intermediate
__device__ float  d_SoS[NPIX];
__device__ float  d_hA[(size_t)MAXM*128];
__device__ float  d_hB[(size_t)MAXM*128];
__device__ float  d_wfs[NTH];
__device__ float2 d_tw[256];              // e^{-i pi n / 256}
__device__ float  d_gw[256];              // Gaussian window 1D factors
__device__ double d_acc[3];               // data, tv, l1 accumulators

// ---------------- helpers ----------------
__device__ __forceinline__ float blockReduce(float v){
    __shared__ float red[32];
    int lane = threadIdx.x & 31, w = threadIdx.x >> 5;
    #pragma unroll
    for (int o = 16; o; o >>= 1) v += __shfl_down_sync(0xffffffffu, v, o);
    __syncthreads();
    if (lane == 0) red[w] = v;
    __syncthreads();
    float r = 0.f;
    if (w == 0){
        int nw = (blockDim.x + 31) >> 5;
        r = (lane < nw) ? red[lane] : 0.f;
        #pragma unroll
        for (int o = 16; o; o >>= 1) r += __shfl_down_sync(0xffffffffu, r, o);
    }
    __syncthreads();
    return r;  // valid on thread 0
}

// packed fp32x2 helpers (Blackwell f32x2 pipe; per-lane .rn rounding)
__device__ __forceinline__ unsigned long long pk2(float lo, float hi){
    unsigned long long r;
    asm("mov.b64 %0, {%1, %2};" : "=l"(r) : "f"(lo), "f"(hi));
    return r;
}
__device__ __forceinline__ unsigned long long fma2(unsigned long long a,
                                                   unsigned long long b,
                                                   unsigned long long c){
    unsigned long long d;
    asm("fma.rn.f32x2 %0, %1, %2, %3;" : "=l"(d) : "l"(a), "l"(b), "l"(c));
    return d;
}
__device__ __forceinline__ void upk2(unsigned long long v, float& lo, float& hi){
    asm("mov.b64 {%0, %1}, %2;" : "=f"(lo), "=f"(hi) : "l"(v));
}

__device__ __forceinline__ float2 cmulf(float2 x, float2 y){
    return make_float2(x.x*y.x - x.y*y.y, x.x*y.y + x.y*y.x);
}

// 1D interpolation over the 240-point theta grid (matches reference _interp1d)
__device__ __forceinline__ float interp_wf(float xn, const float* wf){
    const double step = TWO_PI_D / 239.0;
    const float dxg = (float)step;
    float t = xn / dxg;
    int fi = (int)floorf(t); fi = fi < 0 ? 0 : (fi > 239 ? 239 : fi);
    int ci = (int)ceilf(t);  ci = ci < 0 ? 0 : (ci > 239 ? 239 : ci);
    float yc = wf[ci];
    if (ci == fi) return yc;
    float yf = wf[fi];
    float xf = (float)((double)fi * step);
    float xc = (float)((double)ci * step);
    return yf + (yc - yf) * (xn - xf) / (xc - xf);
}

// Mixed-radix Stockham 512-pt FFT: 1 radix-2 stage + 4 radix-4 stages.
// 128 lanes per line. tw[n] = e^{-i pi n/256}. inv=true conjugates.
// Verified: general Stockham DIF rule reproduces the radix-2 ladder exactly;
// radix-4 combine hand-checked on N=8 (radix-2 then radix-4 == DFT_8).
__device__ __forceinline__ float2* fft512r4(float2* a, float2* b,
                                            const float2* tw, int lane, bool inv){
    float2* src = a; float2* dst = b;
    const float sgn = inv ? -1.f : 1.f;
    // stage 0: radix-2, m=1 (256 butterflies, 2 per thread)
    __syncthreads();
    #pragma unroll
    for (int h = 0; h < 2; h++){
        int j = lane + h*128;
        float2 c0 = src[j];
        float2 c1 = src[j + 256];
        float2 w = tw[j];               // e^{-i 2pi j/512}
        float wy = sgn * w.y;
        float dx = c0.x - c1.x, dy = c0.y - c1.y;
        dst[2*j]     = make_float2(c0.x + c1.x, c0.y + c1.y);
        dst[2*j + 1] = make_float2(w.x*dx - wy*dy, w.x*dy + wy*dx);
    }
    { float2* t = src; src = dst; dst = t; }
    // stages 1..4: radix-4, m = 2, 8, 32, 128 (1 butterfly per thread)
    #pragma unroll
    for (int s = 0; s < 4; s++){
        const int m = 2 << (2*s);       // 2, 8, 32, 128
        __syncthreads();
        int j = lane / m;
        int k = lane - j*m;
        int base = j*m + k;             // == lane, but keep explicit form
        float2 a0 = src[base];
        float2 a1 = src[base + 128];
        float2 a2 = src[base + 256];
        float2 a3 = src[base + 384];
        int n1 = j*m;                   // <= 126 -> 2*n1 <= 252 < 256
        float2 t1 = tw[n1];
        float2 t2 = tw[2*n1];
        float2 w1 = make_float2(t1.x, sgn*t1.y);
        float2 w2 = make_float2(t2.x, sgn*t2.y);
        float2 w3 = cmulf(w1, w2);
        float2 S02 = make_float2(a0.x + a2.x, a0.y + a2.y);
        float2 D02 = make_float2(a0.x - a2.x, a0.y - a2.y);
        float2 S13 = make_float2(a1.x + a3.x, a1.y + a3.y);
        float2 D13 = make_float2(a1.x - a3.x, a1.y - a3.y);
        float2 B0 = make_float2(S02.x + S13.x, S02.y + S13.y);
        float2 B2 = make_float2(S02.x - S13.x, S02.y - S13.y);
        // forward: B1 = D02 - i*D13, B3 = D02 + i*D13; inverse swaps
        float2 B1 = make_float2(D02.x + sgn*D13.y, D02.y - sgn*D13.x);
        float2 B3 = make_float2(D02.x - sgn*D13.y, D02.y + sgn*D13.x);
        int ob = 4*j*m + k;
        dst[ob]       = B0;
        dst[ob + m]   = cmulf(w1, B1);
        dst[ob + 2*m] = cmulf(w2, B2);
        dst[ob + 3*m] = cmulf(w3, B3);
        { float2* t = src; src = dst; dst = t; }
    }
    __syncthreads();
    return src;
}

// ---------------- kernels ----------------
// SoS fill + (block 0) twiddle/window/accumulator init
__global__ void k_prep(){
    int p = blockIdx.x * 256 + threadIdx.x;
    d_SoS[p] = 1499.363f;
    if (blockIdx.x == 0){
        int n = threadIdx.x;
        float s, c;
        sincosf(PI_F * (float)n / 256.f, &s, &c);
        d_tw[n] = make_float2(c, -s);
        double ax  = (double)n - 127.5;
        double sig = 37.5 / sqrt(2.0 * log(2.0));
        d_gw[n] = (float)exp(-ax * ax / (2.0 * sig * sig));
        if (n < 3) d_acc[n] = 0.0;
    }
}

__global__ void k_siren1(const float* __restrict__ mg, const float* __restrict__ W1,
                         const float* __restrict__ b1, int M){
    int p = blockIdx.x; int o = threadIdx.x;
    if (p >= M) return;
    float x0 = mg[2*p], x1 = mg[2*p+1];
    float pre = x0 * W1[o] + x1 * W1[128 + o] + b1[o];
    d_hA[(size_t)p*128 + o] = sinf(30.f * pre);
}

// hidden layer as tiled SGEMM: 64 points x 128 outputs per block, 256 threads,
// 4x8 register tile per thread. Inner product in packed fma.rn.f32x2; the W
// operand is loaded DIRECTLY as u64 pairs from smem (no mov.b64 packing).
__global__ __launch_bounds__(256) void k_mid(const float* __restrict__ W,
                                             const float* __restrict__ b,
                                             int M, int dir){
    __shared__ __align__(16) float As[64][KC + 4];  // [p][k], row = 144B
    __shared__ __align__(16) float Ws[KC][128];     // [k][o], row = 512B
    const float* src = dir ? d_hB : d_hA;
    float*       dst = dir ? d_hA : d_hB;
    int p0  = blockIdx.x * 64;
    int tid = threadIdx.x;
    int tx  = tid & 15, ty = tid >> 4;
    unsigned long long acc2[4][4];
    const unsigned long long z2 = 0ull;   // (0.f, 0.f)
    #pragma unroll
    for (int u = 0; u < 4; u++)
        #pragma unroll
        for (int v = 0; v < 4; v++) acc2[u][v] = z2;

    for (int kc = 0; kc < 128; kc += KC){
        // A tile: 64 points x KC k-values = 512 float4 loads, 2 per thread
        #pragma unroll
        for (int q = 0; q < 2; q++){
            int f  = q*256 + tid;
            int p  = f >> 3;           // 8 float4 per point (KC/4 = 8)
            int kq = f & 7;
            float4 v = make_float4(0.f, 0.f, 0.f, 0.f);
            if (p0 + p < M)
                v = *reinterpret_cast<const float4*>(&src[(size_t)(p0+p)*128 + kc + kq*4]);
            *reinterpret_cast<float4*>(&As[p][kq*4]) = v;
        }
        // W tile: KC rows x 128 outputs = 1024 float4 loads, 4 per thread
        #pragma unroll
        for (int q = 0; q < 4; q++){
            int f  = q*256 + tid;
            int kr = f >> 5;
            int oq = f & 31;
            *reinterpret_cast<float4*>(&Ws[kr][oq*4]) =
                *reinterpret_cast<const float4*>(&W[(size_t)(kc+kr)*128 + oq*4]);
        }
        __syncthreads();
        #pragma unroll
        for (int k4 = 0; k4 < KC/4; k4++){
            float4 av[4];
            #pragma unroll
            for (int u = 0; u < 4; u++)
                av[u] = *reinterpret_cast<const float4*>(&As[ty*4 + u][k4*4]);
            #pragma unroll
            for (int kk = 0; kk < 4; kk++){
                int k = k4*4 + kk;
                const unsigned long long* wp0 =
                    reinterpret_cast<const unsigned long long*>(&Ws[k][tx*4]);
                const unsigned long long* wp1 =
                    reinterpret_cast<const unsigned long long*>(&Ws[k][64 + tx*4]);
                unsigned long long w2[4] = { wp0[0], wp0[1], wp1[0], wp1[1] };
                #pragma unroll
                for (int u = 0; u < 4; u++){
                    float aa = reinterpret_cast<const float*>(&av[u])[kk];
                    unsigned long long aa2 = pk2(aa, aa);
                    #pragma unroll
                    for (int v = 0; v < 4; v++) acc2[u][v] = fma2(aa2, w2[v], acc2[u][v]);
                }
            }
        }
        __syncthreads();
    }
    // epilogue: unpack, add bias, sin, store
    float bo[8];
    #pragma unroll
    for (int v = 0; v < 4; v++){
        bo[v]     = b[tx*4 + v];
        bo[v + 4] = b[64 + tx*4 + v];
    }
    #pragma unroll
    for (int u = 0; u < 4; u++){
        int p = p0 + ty*4 + u;
        if (p < M){
            float a[8];
            upk2(acc2[u][0], a[0], a[1]);
            upk2(acc2[u][1], a[2], a[3]);
            upk2(acc2[u][2], a[4], a[5]);
            upk2(acc2[u][3], a[6], a[7]);
            float4 r0, r1;
            r0.x = sinf(30.f*(a[0] + bo[0]));
            r0.y = sinf(30.f*(a[1] + bo[1]));
            r0.z = sinf(30.f*(a[2] + bo[2]));
            r0.w = sinf(30.f*(a[3] + bo[3]));
            r1.x = sinf(30.f*(a[4] + bo[4]));
            r1.y = sinf(30.f*(a[5] + bo[5]));
            r1.z = sinf(30.f*(a[6] + bo[6]));
            r1.w = sinf(30.f*(a[7] + bo[7]));
            *reinterpret_cast<float4*>(&dst[(size_t)p*128 + tx*4])      = r0;
            *reinterpret_cast<float4*>(&dst[(size_t)p*128 + 64 + tx*4]) = r1;
        }
    }
}

__global__ void k_siren_out(const float* __restrict__ W4, const float* __restrict__ b4,
                            const int* __restrict__ mask_idx, int M){
    int p    = blockIdx.x * 4 + (threadIdx.x >> 5);
    int lane = threadIdx.x & 31;
    if (p >= M) return;
    float acc = 0.f;
    for (int k = lane; k < 128; k += 32) acc += d_hA[(size_t)p*128 + k] * W4[k];
    #pragma unroll
    for (int o = 16; o; o >>= 1) acc += __shfl_down_sync(0xffffffffu, acc, o);
    if (lane == 0) d_SoS[mask_idx[p]] = (acc + b4[0]) * 170.f + 1550.f;
}

__global__ void k_wavefront(const float* __restrict__ xq_, const float* __restrict__ yq_,
                            const float* __restrict__ x_vec, const float* __restrict__ y_vec){
    int it = blockIdx.x;
    int j  = threadIdx.x;
    float xq = xq_[0], yq = yq_[0];
    float th  = (float)((double)it * (TWO_PI_D / 239.0));
    float r   = sqrtf(xq*xq + yq*yq);
    float phi = atan2f(xq, yq);
    float s   = sinf(th - phi), cd = cosf(th - phi);
    float rs  = r * s;
    float disc = 6.4e-5f - rs*rs; if (disc < 0.f) disc = 0.f;
    float sq = sqrtf(disc);
    float l  = (r < 0.008f) ? (sq + r*cd) : (2.f * sq * ((cd >= 0.f) ? 1.f : 0.f));
    float x0 = x_vec[0], dxv = x_vec[1] - x_vec[0];
    float y0 = y_vec[0], dyv = y_vec[1] - y_vec[0];
    float sth = sinf(th), cth = cosf(th);
    __shared__ float fint[NINT];
    __shared__ float xs[NINT];
    if (j < NINT){
        float step = (float)j / 249.0f;
        float xsj  = l * step;
        int xi = (int)rintf((xq - xsj*sth - x0) / dxv);
        int yi = (int)rintf((yq - xsj*cth - y0) / dyv);
        int ry = (((-yi) % 512) + 512) % 512;
        int rx = (((xi) % 512) + 512) % 512;
        fint[j] = 1.0f - 1500.0f / d_SoS[ry*512 + rx];
        xs[j] = xsj;
    }
    __syncthreads();
    float term = 0.f;
    if (j < NINT - 1) term = 0.5f * (fint[j] + fint[j+1]) * (xs[j+1] - xs[j]);
    float tot = blockReduce(term);
    if (j == 0) d_wfs[it] = tot;
}

// Row FFT of ifftshift(pad(y*GWIN)): rows are REAL, so pack two nonzero rows
// as one complex FFT and unpack by conjugate symmetry. 128 row-pairs/image.
__global__ void k_fft_rows_Y(const float* __restrict__ y_img){
    __shared__ float2 s0[512];
    __shared__ float2 s1[512];
    __shared__ float2 stw[256];
    int b = blockIdx.x; int a = b >> 7; int q = b & 127;
    int r1 = 2*q, r2 = 2*q + 1;
    int i1 = (r1 < 128) ? r1 : r1 + 256;       // nonzero output rows
    int i2 = (r2 < 128) ? r2 : r2 + 256;
    int lane = threadIdx.x;
    stw[lane]       = d_tw[lane];
    stw[lane + 128] = d_tw[lane + 128];
    int si1 = (i1 + 256) & 511;                // in [128,384)
    int si2 = (i2 + 256) & 511;
    float gy1 = d_gw[si1 - 128];
    float gy2 = d_gw[si2 - 128];
    const float* row1 = y_img + (size_t)a*65536 + (si1-128)*256;
    const float* row2 = y_img + (size_t)a*65536 + (si2-128)*256;
    for (int j = lane; j < 512; j += 128){
        int sj = (j + 256) & 511;
        float v1 = 0.f, v2 = 0.f;
        if (sj >= 128 && sj < 384){
            float gx = d_gw[sj - 128];
            v1 = row1[sj-128] * (gy1 * gx);
            v2 = row2[sj-128] * (gy2 * gx);
        }
        s0[j] = make_float2(v1, v2);           // z = row1 + i*row2
    }
    float2* res = fft512r4(s0, s1, stw, lane, false);
    float2* o1 = &d_Y[((size_t)a*512 + i1) * 512];
    float2* o2 = &d_Y[((size_t)a*512 + i2) * 512];
    for (int j = lane; j < 512; j += 128){
        float2 zj = res[j];
        float2 zm = res[(512 - j) & 511];
        o1[j] = make_float2(0.5f*(zj.x + zm.x), 0.5f*(zj.y - zm.y));
        o2[j] = make_float2(0.5f*(zj.y + zm.y), 0.5f*(zm.x - zj.x));
    }
}

// Column FFT; input rows 128..383 known-zero (never written) -> synthesize zeros.
// Stores only rows 0..256 (k_solve reads only those; Nyquist-col extras use
// Y-index-Hermitian symmetry against rows 1..255).
__global__ void k_fft_cols_Y(){
    __shared__ float2 s0[4][514];
    __shared__ float2 s1[4][514];
    __shared__ float2 stw[256];
    int blk = blockIdx.x; int a = blk >> 7; int j0 = (blk & 127) << 2;
    int tx = threadIdx.x, ty = threadIdx.y;
    int ltid = tx + ty * 4;
    if (ltid < 256) stw[ltid] = d_tw[ltid];
    float2* base = &d_Y[(size_t)a * NPIX];
    s0[tx][ty]       = base[ty*512 + j0 + tx];
    s0[tx][ty + 128] = make_float2(0.f, 0.f);
    s0[tx][ty + 256] = make_float2(0.f, 0.f);
    s0[tx][ty + 384] = base[(ty + 384)*512 + j0 + tx];
    float2* res = fft512r4(&s0[tx][0], &s1[tx][0], stw, ty, false);
    #pragma unroll
    for (int rr = 0; rr < 3; rr++){
        int i = ty + rr*128;
        if (i <= 256) base[i*512 + j0 + tx] = res[i];
    }
}

// Fused: H on the fly + Wiener solve + data loss on the Hermitian half-plane,
// with EXACT Nyquist handling:
//  - rows 1..255, j != 256: weight 2, conj-mirror write to (512-i, (512-j)&511)
//  - rows 1..255, j == 256: weight 1, NO mirror (H not index-Hermitian at col 256)
//  - row 0: within-row mirror valid (fi=0); j in 1..255 weight 2, j=0/256 weight 1
//  - row 256 (Nyquist): ALL j computed directly, weight 1, no mirror
//  - extra block: pixels (r, 256), r=257..511 computed directly (weight 1),
//    reading Y[r][256] = conj(Y[512-r][256]) (exact DFT identity).
__global__ void k_solve(const float* __restrict__ delays){
    __shared__ float swf[NTH];
    __shared__ float sd[ND];
    int t = threadIdx.x;
    if (t < NTH) swf[t] = d_wfs[t];
    if (t < ND)  sd[t]  = delays[t];
    __syncthreads();
    int i = 0, j = 0;
    bool yconj = false, valid = true;
    int mirror = 0;                 // 0 none, 1 row0-within, 2 full
    float wgt = 0.f;
    if (blockIdx.x < 514){
        int p = blockIdx.x * 256 + t;          // p < 257*512
        i = p >> 9; j = p & 511;
        if (i == 256){
            wgt = 1.f;                          // Nyquist row: direct, all j
        } else if (i == 0){
            wgt = (j == 0 || j == 256) ? 1.f : (j < 256 ? 2.f : 0.f);
            if (j >= 1 && j <= 255) mirror = 1;
        } else {
            if (j == 256){ wgt = 1.f; }        // Nyquist col: direct, no mirror
            else { wgt = 2.f; mirror = 2; }
        }
        if (wgt == 0.f) valid = false;
    } else {
        // extra block: (r, 256) for r = 257..511
        if (t < 255){ i = 257 + t; j = 256; yconj = true; wgt = 1.f; }
        else valid = false;
    }
    float loc = 0.f;
    if (valid){
        float fi = (float)(i < 256 ? i : i - 512) * 48.828125f;
        float fj = (float)(j < 256 ? j : j - 512) * 48.828125f;
        float kk = TWO_PI_F * sqrtf(fi*fi + fj*fj);
        float th = atan2f(fj, fi);
        if (th < 0.f) th += TWO_PI_F;
        float w  = interp_wf(th, swf);
        float tp = th + PI_F;
        tp = tp - floorf(tp / TWO_PI_F) * TWO_PI_F;
        float wpi = interp_wf(tp, swf);
        float C = 0.5f * kk * (w + wpi);
        float S = 0.5f * kk * (w - wpi);
        float sS, cS; __sincosf(S, &sS, &cS);
        int ysrc = yconj ? ((512 - i)*512 + 256) : (i*512 + j);
        float ysign = yconj ? -1.f : 1.f;
        float Syx = 0.f, Syy = 0.f, lhs = 0.f, sy2 = 0.f, syh = 0.f;
        #pragma unroll 4
        for (int a = 0; a < ND; a++){
            float c = __cosf(C - kk * sd[a]);      // h_a = c * e^{iS}
            float2 y = d_Y[(size_t)a*NPIX + ysrc];
            y.y *= ysign;
            Syx += y.x * c;
            Syy += y.y * c;
            float c2 = c * c;
            lhs += c2;
            float ay2 = y.x*y.x + y.y*y.y;
            sy2 += ay2;
            syh += sqrtf(ay2 * c2);                // |y_a| * |h_a|
        }
        float inv = 1.f / lhs;
        // X = conj(e^{iS}) * Sy / lhs
        float xr = (Syx*cS + Syy*sS) * inv;
        float xi = (Syy*cS - Syx*sS) * inv;
        d_Xf[i*512 + j] = make_float2(xr, xi);
        if (mirror == 2){
            d_Xf[(512 - i)*512 + ((512 - j) & 511)] = make_float2(xr, -xi);
        } else if (mirror == 1){
            d_Xf[512 - j] = make_float2(xr, -xi);  // row 0, cols 257..511
        }
        float xm = sqrtf(xr*xr + xi*xi);
        loc = wgt * kk*kk * (sy2 - 2.f*xm*syh + xm*xm*lhs);
    }
    float tot = blockReduce(loc);
    if (t == 0) atomicAdd(&d_acc[0], (double)tot);
}

__global__ void k_ifft_rows(){
    __shared__ float2 s0[512];
    __shared__ float2 s1[512];
    __shared__ float2 stw[256];
    int i = blockIdx.x; int lane = threadIdx.x;
    stw[lane]       = d_tw[lane];
    stw[lane + 128] = d_tw[lane + 128];
    for (int j = lane; j < 512; j += 128) s0[j] = d_Xf[i*512 + j];
    float2* res = fft512r4(s0, s1, stw, lane, true);
    const float sc = 1.f / 512.f;
    for (int j = lane; j < 512; j += 128){
        float2 v = res[j];
        d_T[i*512 + j] = make_float2(v.x * sc, v.y * sc);
    }
}

// inverse FFT columns + fftshift + real -> x_rec directly into d_out
__global__ void k_ifft_cols_out(float* __restrict__ out){
    __shared__ float2 s0[4][514];
    __shared__ float2 s1[4][514];
    __shared__ float2 stw[256];
    int j0 = (blockIdx.x & 127) << 2;
    int tx = threadIdx.x, ty = threadIdx.y;
    int ltid = tx + ty * 4;
    if (ltid < 256) stw[ltid] = d_tw[ltid];
    #pragma unroll
    for (int rr = 0; rr < 4; rr++){
        int i = ty + rr*128;
        s0[tx][i] = d_T[i*512 + j0 + tx];
    }
    float2* res = fft512r4(&s0[tx][0], &s1[tx][0], stw, ty, true);
    const float sc = 1.f / 512.f;
    int oj = ((j0 + tx) + 256) & 511;
    #pragma unroll
    for (int rr = 0; rr < 4; rr++){
        int i = ty + rr*128;
        int oi = (i + 256) & 511;
        out[oi*512 + oj] = res[i].x * sc;
    }
}

__global__ void k_tv_l1(const float* __restrict__ mask, float* __restrict__ out){
    int p = blockIdx.x * 256 + threadIdx.x;
    int i = p >> 9, j = p & 511;
    float S = d_SoS[p];
    out[NPIX + p] = S;                      // SoS copy fused here
    float m = mask[p];
    float tv = 0.f;
    if (i > 0) tv += fabsf((S - d_SoS[p - 512]) * m);
    if (j > 0) tv += fabsf((S - d_SoS[p - 1]) * m);
    float l1 = fabsf(S - 1550.f) * m;
    float t1 = blockReduce(tv);
    if (threadIdx.x == 0) atomicAdd(&d_acc[1], (double)t1);
    float t2 = blockReduce(l1);
    if (threadIdx.x == 0) atomicAdd(&d_acc[2], (double)t2);
}

__global__ void k_final(float* __restrict__ out){
    double data = d_acc[0] / (double)((size_t)ND * NPIX);
    double loss = data + 0.001 * d_acc[1] + 0.001 * (d_acc[2] / (double)NPIX);
    out[2 * NPIX] = (float)loss;
}

// ---------------- launch ----------------
extern "C" void kernel_launch(void* const* d_in, const int* in_sizes, int n_in,
                              void* d_out, int out_size){
    const float* W1  = (const float*)d_in[0];
    const float* b1  = (const float*)d_in[1];
    const float* W2  = (const float*)d_in[2];
    const float* b2  = (const float*)d_in[3];
    const float* W3  = (const float*)d_in[4];
    const float* b3  = (const float*)d_in[5];
    const float* W4  = (const float*)d_in[6];
    const float* b4  = (const float*)d_in[7];
    const float* y_img   = (const float*)d_in[8];
    const float* delays  = (const float*)d_in[9];
    const float* xq      = (const float*)d_in[10];
    const float* yq      = (const float*)d_in[11];
    const float* mgrid   = (const float*)d_in[12];
    const float* mask    = (const float*)d_in[13];
    const int*   mask_idx= (const int*)  d_in[14];
    const float* x_vec   = (const float*)d_in[15];
    const float* y_vec   = (const float*)d_in[16];
    int M = in_sizes[14];
    if (M > MAXM) M = MAXM;
    float* out = (float*)d_out;

    k_prep<<<NPIX/256, 256>>>();

    // SIREN
    k_siren1<<<M, 128>>>(mgrid, W1, b1, M);
    k_mid<<<(M + 63) / 64, 256>>>(W2, b2, M, 0);     // hA -> hB
    k_mid<<<(M + 63) / 64, 256>>>(W3, b3, M, 1);     // hB -> hA
    k_siren_out<<<(M + 3) / 4, 128>>>(W4, b4, mask_idx, M);

    // wavefront
    k_wavefront<<<NTH, 256>>>(xq, yq, x_vec, y_vec);

    // Y = fft2(ifftshift(pad(y*GWIN)))  (zero rows skipped, real rows packed,
    // only rows 0..256 stored) — radix-4 Stockham
    k_fft_rows_Y<<<ND*128, 128>>>(y_img);
    k_fft_cols_Y<<<ND*128, dim3(4, 128)>>>();

    // fused H + Wiener solve + data loss (half-plane + exact Nyquist handling)
    k_solve<<<515, 256>>>(delays);

    // reconstruction (radix-4 Stockham)
    k_ifft_rows<<<512, 128>>>();
    k_ifft_cols_out<<<128, dim3(4, 128)>>>(out);

    // losses + SoS copy
    k_tv_l1<<<NPIX/256, 256>>>(mask, out);
    k_final<<<1, 1>>>(out);
}

// round 16
// speedup vs baseline: 1.7115x; 1.0499x over previous
#include <cuda_runtime.h>
#include <math.h>

#define NPAD  512
#define NPIX  (512*512)
#define ND    32
#define NTH   240
#define NINT  250
#define NIMG  256
#define MAXM  40960
#define KC    32
#define PI_F      3.14159265358979323846f
#define TWO_PI_F  6.28318530717958647692f
#define TWO_PI_D  6.283185307179586476925286766559

// ---------------- scratch (static device globals; no allocations) ----------
__device__ float2 d_Y[(size_t)ND*NPIX];   // FFT of padded windowed images
__device__ float2 d_Xf[NPIX];             // Wiener solution in freq domain
__device__ float2 d_T[NPIX];              // ifft intermediate
__device__ float  d_SoS[NPIX];
__device__ float  d_hA[(size_t)MAXM*128];
__device__ float  d_hB[(size_t)MAXM*128];
__device__ float  d_wfs[NTH];
__device__ float2 d_tw[256];              // e^{-i pi n / 256}
__device__ float  d_gw[256];              // Gaussian window 1D factors
__device__ double d_acc[3];               // data, tv, l1 accumulators

// ---------------- helpers ----------------
__device__ __forceinline__ float blockReduce(float v){
    __shared__ float red[32];
    int lane = threadIdx.x & 31, w = threadIdx.x >> 5;
    #pragma unroll
    for (int o = 16; o; o >>= 1) v += __shfl_down_sync(0xffffffffu, v, o);
    __syncthreads();
    if (lane == 0) red[w] = v;
    __syncthreads();
    float r = 0.f;
    if (w == 0){
        int nw = (blockDim.x + 31) >> 5;
        r = (lane < nw) ? red[lane] : 0.f;
        #pragma unroll
        for (int o = 16; o; o >>= 1) r += __shfl_down_sync(0xffffffffu, r, o);
    }
    __syncthreads();
    return r;  // valid on thread 0
}

// packed fp32x2 helpers (Blackwell f32x2 pipe; per-lane .rn rounding)
__device__ __forceinline__ unsigned long long fma2(unsigned long long a,
                                                   unsigned long long b,
                                                   unsigned long long c){
    unsigned long long d;
    asm("fma.rn.f32x2 %0, %1, %2, %3;" : "=l"(d) : "l"(a), "l"(b), "l"(c));
    return d;
}
__device__ __forceinline__ void upk2(unsigned long long v, float& lo, float& hi){
    asm("mov.b64 {%0, %1}, %2;" : "=f"(lo), "=f"(hi) : "l"(v));
}

__device__ __forceinline__ float2 cmulf(float2 x, float2 y){
    return make_float2(x.x*y.x - x.y*y.y, x.x*y.y + x.y*y.x);
}

// 1D interpolation over the 240-point theta grid (matches reference _interp1d)
__device__ __forceinline__ float interp_wf(float xn, const float* wf){
    const double step = TWO_PI_D / 239.0;
    const float dxg = (float)step;
    float t = xn / dxg;
    int fi = (int)floorf(t); fi = fi < 0 ? 0 : (fi > 239 ? 239 : fi);
    int ci = (int)ceilf(t);  ci = ci < 0 ? 0 : (ci > 239 ? 239 : ci);
    float yc = wf[ci];
    if (ci == fi) return yc;
    float yf = wf[fi];
    float xf = (float)((double)fi * step);
    float xc = (float)((double)ci * step);
    return yf + (yc - yf) * (xn - xf) / (xc - xf);
}

// Mixed-radix Stockham 512-pt FFT: 1 radix-2 stage + 4 radix-4 stages.
// 128 lanes per line. tw[n] = e^{-i pi n/256}. inv=true conjugates.
__device__ __forceinline__ float2* fft512r4(float2* a, float2* b,
                                            const float2* tw, int lane, bool inv){
    float2* src = a; float2* dst = b;
    const float sgn = inv ? -1.f : 1.f;
    // stage 0: radix-2, m=1 (256 butterflies, 2 per thread)
    __syncthreads();
    #pragma unroll
    for (int h = 0; h < 2; h++){
        int j = lane + h*128;
        float2 c0 = src[j];
        float2 c1 = src[j + 256];
        float2 w = tw[j];               // e^{-i 2pi j/512}
        float wy = sgn * w.y;
        float dx = c0.x - c1.x, dy = c0.y - c1.y;
        dst[2*j]     = make_float2(c0.x + c1.x, c0.y + c1.y);
        dst[2*j + 1] = make_float2(w.x*dx - wy*dy, w.x*dy + wy*dx);
    }
    { float2* t = src; src = dst; dst = t; }
    // stages 1..4: radix-4, m = 2, 8, 32, 128 (1 butterfly per thread)
    #pragma unroll
    for (int s = 0; s < 4; s++){
        const int m = 2 << (2*s);       // 2, 8, 32, 128
        __syncthreads();
        int j = lane / m;
        int k = lane - j*m;
        int base = j*m + k;             // == lane, but keep explicit form
        float2 a0 = src[base];
        float2 a1 = src[base + 128];
        float2 a2 = src[base + 256];
        float2 a3 = src[base + 384];
        int n1 = j*m;                   // <= 126 -> 2*n1 <= 252 < 256
        float2 t1 = tw[n1];
        float2 t2 = tw[2*n1];
        float2 w1 = make_float2(t1.x, sgn*t1.y);
        float2 w2 = make_float2(t2.x, sgn*t2.y);
        float2 w3 = cmulf(w1, w2);
        float2 S02 = make_float2(a0.x + a2.x, a0.y + a2.y);
        float2 D02 = make_float2(a0.x - a2.x, a0.y - a2.y);
        float2 S13 = make_float2(a1.x + a3.x, a1.y + a3.y);
        float2 D13 = make_float2(a1.x - a3.x, a1.y - a3.y);
        float2 B0 = make_float2(S02.x + S13.x, S02.y + S13.y);
        float2 B2 = make_float2(S02.x - S13.x, S02.y - S13.y);
        // forward: B1 = D02 - i*D13, B3 = D02 + i*D13; inverse swaps
        float2 B1 = make_float2(D02.x + sgn*D13.y, D02.y - sgn*D13.x);
        float2 B3 = make_float2(D02.x - sgn*D13.y, D02.y + sgn*D13.x);
        int ob = 4*j*m + k;
        dst[ob]       = B0;
        dst[ob + m]   = cmulf(w1, B1);
        dst[ob + 2*m] = cmulf(w2, B2);
        dst[ob + 3*m] = cmulf(w3, B3);
        { float2* t = src; src = dst; dst = t; }
    }
    __syncthreads();
    return src;
}

// ---------------- kernels ----------------
// SoS fill + (block 0) twiddle/window/accumulator init
__global__ void k_prep(){
    int p = blockIdx.x * 256 + threadIdx.x;
    d_SoS[p] = 1499.363f;
    if (blockIdx.x == 0){
        int n = threadIdx.x;
        float s, c;
        sincosf(PI_F * (float)n / 256.f, &s, &c);
        d_tw[n] = make_float2(c, -s);
        double ax  = (double)n - 127.5;
        double sig = 37.5 / sqrt(2.0 * log(2.0));
        d_gw[n] = (float)exp(-ax * ax / (2.0 * sig * sig));
        if (n < 3) d_acc[n] = 0.0;
    }
}

__global__ void k_siren1(const float* __restrict__ mg, const float* __restrict__ W1,
                         const float* __restrict__ b1, int M){
    int p = blockIdx.x; int o = threadIdx.x;
    if (p >= M) return;
    float x0 = mg[2*p], x1 = mg[2*p+1];
    float pre = x0 * W1[o] + x1 * W1[128 + o] + b1[o];
    d_hA[(size_t)p*128 + o] = sinf(30.f * pre);
}

// hidden layer as tiled SGEMM: 64 points x 128 outputs per block, 256 threads,
// 4x8 register tile per thread. Inner product in packed fma.rn.f32x2. BOTH
// operands load directly as u64: W as adjacent output pairs, A from a smem
// tile stored PRE-DUPLICATED (As[p][2k] = As[p][2k+1] = a[p][k]) so the
// inner loop has zero mov.b64 packing.
__global__ __launch_bounds__(256) void k_mid(const float* __restrict__ W,
                                             const float* __restrict__ b,
                                             int M, int dir){
    __shared__ __align__(16) float As[64][2*KC + 4]; // duplicated pairs, row=272B
    __shared__ __align__(16) float Ws[KC][128];      // [k][o], row = 512B
    const float* src = dir ? d_hB : d_hA;
    float*       dst = dir ? d_hA : d_hB;
    int p0  = blockIdx.x * 64;
    int tid = threadIdx.x;
    int tx  = tid & 15, ty = tid >> 4;
    unsigned long long acc2[4][4];
    const unsigned long long z2 = 0ull;   // (0.f, 0.f)
    #pragma unroll
    for (int u = 0; u < 4; u++)
        #pragma unroll
        for (int v = 0; v < 4; v++) acc2[u][v] = z2;

    for (int kc = 0; kc < 128; kc += KC){
        // A tile: 64 points x KC k-values, written duplicated: 2 float4 per load
        #pragma unroll
        for (int q = 0; q < 2; q++){
            int f  = q*256 + tid;
            int p  = f >> 3;           // 8 float4 per point (KC/4 = 8)
            int kq = f & 7;
            float4 v = make_float4(0.f, 0.f, 0.f, 0.f);
            if (p0 + p < M)
                v = *reinterpret_cast<const float4*>(&src[(size_t)(p0+p)*128 + kc + kq*4]);
            float4 lo = make_float4(v.x, v.x, v.y, v.y);
            float4 hi = make_float4(v.z, v.z, v.w, v.w);
            *reinterpret_cast<float4*>(&As[p][kq*8])     = lo;
            *reinterpret_cast<float4*>(&As[p][kq*8 + 4]) = hi;
        }
        // W tile: KC rows x 128 outputs = 1024 float4 loads, 4 per thread
        #pragma unroll
        for (int q = 0; q < 4; q++){
            int f  = q*256 + tid;
            int kr = f >> 5;
            int oq = f & 31;
            *reinterpret_cast<float4*>(&Ws[kr][oq*4]) =
                *reinterpret_cast<const float4*>(&W[(size_t)(kc+kr)*128 + oq*4]);
        }
        __syncthreads();
        #pragma unroll
        for (int k = 0; k < KC; k++){
            const unsigned long long* wp0 =
                reinterpret_cast<const unsigned long long*>(&Ws[k][tx*4]);
            const unsigned long long* wp1 =
                reinterpret_cast<const unsigned long long*>(&Ws[k][64 + tx*4]);
            unsigned long long w2[4] = { wp0[0], wp0[1], wp1[0], wp1[1] };
            #pragma unroll
            for (int u = 0; u < 4; u++){
                unsigned long long aa2 =
                    *reinterpret_cast<const unsigned long long*>(&As[ty*4 + u][2*k]);
                #pragma unroll
                for (int v = 0; v < 4; v++) acc2[u][v] = fma2(aa2, w2[v], acc2[u][v]);
            }
        }
        __syncthreads();
    }
    // epilogue: unpack, add bias, sin, store
    float bo[8];
    #pragma unroll
    for (int v = 0; v < 4; v++){
        bo[v]     = b[tx*4 + v];
        bo[v + 4] = b[64 + tx*4 + v];
    }
    #pragma unroll
    for (int u = 0; u < 4; u++){
        int p = p0 + ty*4 + u;
        if (p < M){
            float a[8];
            upk2(acc2[u][0], a[0], a[1]);
            upk2(acc2[u][1], a[2], a[3]);
            upk2(acc2[u][2], a[4], a[5]);
            upk2(acc2[u][3], a[6], a[7]);
            float4 r0, r1;
            r0.x = sinf(30.f*(a[0] + bo[0]));
            r0.y = sinf(30.f*(a[1] + bo[1]));
            r0.z = sinf(30.f*(a[2] + bo[2]));
            r0.w = sinf(30.f*(a[3] + bo[3]));
            r1.x = sinf(30.f*(a[4] + bo[4]));
            r1.y = sinf(30.f*(a[5] + bo[5]));
            r1.z = sinf(30.f*(a[6] + bo[6]));
            r1.w = sinf(30.f*(a[7] + bo[7]));
            *reinterpret_cast<float4*>(&dst[(size_t)p*128 + tx*4])      = r0;
            *reinterpret_cast<float4*>(&dst[(size_t)p*128 + 64 + tx*4]) = r1;
        }
    }
}

__global__ void k_siren_out(const float* __restrict__ W4, const float* __restrict__ b4,
                            const int* __restrict__ mask_idx, int M){
    int p    = blockIdx.x * 4 + (threadIdx.x >> 5);
    int lane = threadIdx.x & 31;
    if (p >= M) return;
    float acc = 0.f;
    for (int k = lane; k < 128; k += 32) acc += d_hA[(size_t)p*128 + k] * W4[k];
    #pragma unroll
    for (int o = 16; o; o >>= 1) acc += __shfl_down_sync(0xffffffffu, acc, o);
    if (lane == 0) d_SoS[mask_idx[p]] = (acc + b4[0]) * 170.f + 1550.f;
}

__global__ void k_wavefront(const float* __restrict__ xq_, const float* __restrict__ yq_,
                            const float* __restrict__ x_vec, const float* __restrict__ y_vec){
    int it = blockIdx.x;
    int j  = threadIdx.x;
    float xq = xq_[0], yq = yq_[0];
    float th  = (float)((double)it * (TWO_PI_D / 239.0));
    float r   = sqrtf(xq*xq + yq*yq);
    float phi = atan2f(xq, yq);
    float s   = sinf(th - phi), cd = cosf(th - phi);
    float rs  = r * s;
    float disc = 6.4e-5f - rs*rs; if (disc < 0.f) disc = 0.f;
    float sq = sqrtf(disc);
    float l  = (r < 0.008f) ? (sq + r*cd) : (2.f * sq * ((cd >= 0.f) ? 1.f : 0.f));
    float x0 = x_vec[0], dxv = x_vec[1] - x_vec[0];
    float y0 = y_vec[0], dyv = y_vec[1] - y_vec[0];
    float sth = sinf(th), cth = cosf(th);
    __shared__ float fint[NINT];
    __shared__ float xs[NINT];
    if (j < NINT){
        float step = (float)j / 249.0f;
        float xsj  = l * step;
        int xi = (int)rintf((xq - xsj*sth - x0) / dxv);
        int yi = (int)rintf((yq - xsj*cth - y0) / dyv);
        int ry = (((-yi) % 512) + 512) % 512;
        int rx = (((xi) % 512) + 512) % 512;
        fint[j] = 1.0f - 1500.0f / d_SoS[ry*512 + rx];
        xs[j] = xsj;
    }
    __syncthreads();
    float term = 0.f;
    if (j < NINT - 1) term = 0.5f * (fint[j] + fint[j+1]) * (xs[j+1] - xs[j]);
    float tot = blockReduce(term);
    if (j == 0) d_wfs[it] = tot;
}

// Row FFT of ifftshift(pad(y*GWIN)): rows are REAL, so pack two nonzero rows
// as one complex FFT and unpack by conjugate symmetry. 128 row-pairs/image.
__global__ void k_fft_rows_Y(const float* __restrict__ y_img){
    __shared__ float2 s0[512];
    __shared__ float2 s1[512];
    __shared__ float2 stw[256];
    int b = blockIdx.x; int a = b >> 7; int q = b & 127;
    int r1 = 2*q, r2 = 2*q + 1;
    int i1 = (r1 < 128) ? r1 : r1 + 256;       // nonzero output rows
    int i2 = (r2 < 128) ? r2 : r2 + 256;
    int lane = threadIdx.x;
    stw[lane]       = d_tw[lane];
    stw[lane + 128] = d_tw[lane + 128];
    int si1 = (i1 + 256) & 511;                // in [128,384)
    int si2 = (i2 + 256) & 511;
    float gy1 = d_gw[si1 - 128];
    float gy2 = d_gw[si2 - 128];
    const float* row1 = y_img + (size_t)a*65536 + (si1-128)*256;
    const float* row2 = y_img + (size_t)a*65536 + (si2-128)*256;
    for (int j = lane; j < 512; j += 128){
        int sj = (j + 256) & 511;
        float v1 = 0.f, v2 = 0.f;
        if (sj >= 128 && sj < 384){
            float gx = d_gw[sj - 128];
            v1 = row1[sj-128] * (gy1 * gx);
            v2 = row2[sj-128] * (gy2 * gx);
        }
        s0[j] = make_float2(v1, v2);           // z = row1 + i*row2
    }
    float2* res = fft512r4(s0, s1, stw, lane, false);
    float2* o1 = &d_Y[((size_t)a*512 + i1) * 512];
    float2* o2 = &d_Y[((size_t)a*512 + i2) * 512];
    for (int j = lane; j < 512; j += 128){
        float2 zj = res[j];
        float2 zm = res[(512 - j) & 511];
        o1[j] = make_float2(0.5f*(zj.x + zm.x), 0.5f*(zj.y - zm.y));
        o2[j] = make_float2(0.5f*(zj.y + zm.y), 0.5f*(zm.x - zj.x));
    }
}

// Column FFT; input rows 128..383 known-zero (never written) -> synthesize zeros.
// Stores only rows 0..256 (k_solve reads only those; Nyquist-col extras use
// Y-index-Hermitian symmetry against rows 1..255).
__global__ void k_fft_cols_Y(){
    __shared__ float2 s0[4][514];
    __shared__ float2 s1[4][514];
    __shared__ float2 stw[256];
    int blk = blockIdx.x; int a = blk >> 7; int j0 = (blk & 127) << 2;
    int tx = threadIdx.x, ty = threadIdx.y;
    int ltid = tx + ty * 4;
    if (ltid < 256) stw[ltid] = d_tw[ltid];
    float2* base = &d_Y[(size_t)a * NPIX];
    s0[tx][ty]       = base[ty*512 + j0 + tx];
    s0[tx][ty + 128] = make_float2(0.f, 0.f);
    s0[tx][ty + 256] = make_float2(0.f, 0.f);
    s0[tx][ty + 384] = base[(ty + 384)*512 + j0 + tx];
    float2* res = fft512r4(&s0[tx][0], &s1[tx][0], stw, ty, false);
    #pragma unroll
    for (int rr = 0; rr < 3; rr++){
        int i = ty + rr*128;
        if (i <= 256) base[i*512 + j0 + tx] = res[i];
    }
}

// Fused: H on the fly + Wiener solve + data loss on the Hermitian half-plane,
// with EXACT Nyquist handling:
//  - rows 1..255, j != 256: weight 2, conj-mirror write to (512-i, (512-j)&511)
//  - rows 1..255, j == 256: weight 1, NO mirror (H not index-Hermitian at col 256)
//  - row 0: within-row mirror valid (fi=0); j in 1..255 weight 2, j=0/256 weight 1
//  - row 256 (Nyquist): ALL j computed directly, weight 1, no mirror
//  - extra block: pixels (r, 256), r=257..511 computed directly (weight 1),
//    reading Y[r][256] = conj(Y[512-r][256]) (exact DFT identity).
__global__ void k_solve(const float* __restrict__ delays){
    __shared__ float swf[NTH];
    __shared__ float sd[ND];
    int t = threadIdx.x;
    if (t < NTH) swf[t] = d_wfs[t];
    if (t < ND)  sd[t]  = delays[t];
    __syncthreads();
    int i = 0, j = 0;
    bool yconj = false, valid = true;
    int mirror = 0;                 // 0 none, 1 row0-within, 2 full
    float wgt = 0.f;
    if (blockIdx.x < 514){
        int p = blockIdx.x * 256 + t;          // p < 257*512
        i = p >> 9; j = p & 511;
        if (i == 256){
            wgt = 1.f;                          // Nyquist row: direct, all j
        } else if (i == 0){
            wgt = (j == 0 || j == 256) ? 1.f : (j < 256 ? 2.f : 0.f);
            if (j >= 1 && j <= 255) mirror = 1;
        } else {
            if (j == 256){ wgt = 1.f; }        // Nyquist col: direct, no mirror
            else { wgt = 2.f; mirror = 2; }
        }
        if (wgt == 0.f) valid = false;
    } else {
        // extra block: (r, 256) for r = 257..511
        if (t < 255){ i = 257 + t; j = 256; yconj = true; wgt = 1.f; }
        else valid = false;
    }
    float loc = 0.f;
    if (valid){
        float fi = (float)(i < 256 ? i : i - 512) * 48.828125f;
        float fj = (float)(j < 256 ? j : j - 512) * 48.828125f;
        float kk = TWO_PI_F * sqrtf(fi*fi + fj*fj);
        float th = atan2f(fj, fi);
        if (th < 0.f) th += TWO_PI_F;
        float w  = interp_wf(th, swf);
        float tp = th + PI_F;
        tp = tp - floorf(tp / TWO_PI_F) * TWO_PI_F;
        float wpi = interp_wf(tp, swf);
        float C = 0.5f * kk * (w + wpi);
        float S = 0.5f * kk * (w - wpi);
        float sS, cS; __sincosf(S, &sS, &cS);
        int ysrc = yconj ? ((512 - i)*512 + 256) : (i*512 + j);
        float ysign = yconj ? -1.f : 1.f;
        float Syx = 0.f, Syy = 0.f, lhs = 0.f, sy2 = 0.f, syh = 0.f;
        #pragma unroll 4
        for (int a = 0; a < ND; a++){
            float c = __cosf(C - kk * sd[a]);      // h_a = c * e^{iS}
            float2 y = d_Y[(size_t)a*NPIX + ysrc];
            y.y *= ysign;
            Syx += y.x * c;
            Syy += y.y * c;
            float c2 = c * c;
            lhs += c2;
            float ay2 = y.x*y.x + y.y*y.y;
            sy2 += ay2;
            syh += sqrtf(ay2 * c2);                // |y_a| * |h_a|
        }
        float inv = 1.f / lhs;
        // X = conj(e^{iS}) * Sy / lhs
        float xr = (Syx*cS + Syy*sS) * inv;
        float xi = (Syy*cS - Syx*sS) * inv;
        d_Xf[i*512 + j] = make_float2(xr, xi);
        if (mirror == 2){
            d_Xf[(512 - i)*512 + ((512 - j) & 511)] = make_float2(xr, -xi);
        } else if (mirror == 1){
            d_Xf[512 - j] = make_float2(xr, -xi);  // row 0, cols 257..511
        }
        float xm = sqrtf(xr*xr + xi*xi);
        loc = wgt * kk*kk * (sy2 - 2.f*xm*syh + xm*xm*lhs);
    }
    float tot = blockReduce(loc);
    if (t == 0) atomicAdd(&d_acc[0], (double)tot);
}

__global__ void k_ifft_rows(){
    __shared__ float2 s0[512];
    __shared__ float2 s1[512];
    __shared__ float2 stw[256];
    int i = blockIdx.x; int lane = threadIdx.x;
    stw[lane]       = d_tw[lane];
    stw[lane + 128] = d_tw[lane + 128];
    for (int j = lane; j < 512; j += 128) s0[j] = d_Xf[i*512 + j];
    float2* res = fft512r4(s0, s1, stw, lane, true);
    const float sc = 1.f / 512.f;
    for (int j = lane; j < 512; j += 128){
        float2 v = res[j];
        d_T[i*512 + j] = make_float2(v.x * sc, v.y * sc);
    }
}

// inverse FFT columns + fftshift + real -> x_rec directly into d_out
__global__ void k_ifft_cols_out(float* __restrict__ out){
    __shared__ float2 s0[4][514];
    __shared__ float2 s1[4][514];
    __shared__ float2 stw[256];
    int j0 = (blockIdx.x & 127) << 2;
    int tx = threadIdx.x, ty = threadIdx.y;
    int ltid = tx + ty * 4;
    if (ltid < 256) stw[ltid] = d_tw[ltid];
    #pragma unroll
    for (int rr = 0; rr < 4; rr++){
        int i = ty + rr*128;
        s0[tx][i] = d_T[i*512 + j0 + tx];
    }
    float2* res = fft512r4(&s0[tx][0], &s1[tx][0], stw, ty, true);
    const float sc = 1.f / 512.f;
    int oj = ((j0 + tx) + 256) & 511;
    #pragma unroll
    for (int rr = 0; rr < 4; rr++){
        int i = ty + rr*128;
        int oi = (i + 256) & 511;
        out[oi*512 + oj] = res[i].x * sc;
    }
}

__global__ void k_tv_l1(const float* __restrict__ mask, float* __restrict__ out){
    int p = blockIdx.x * 256 + threadIdx.x;
    int i = p >> 9, j = p & 511;
    float S = d_SoS[p];
    out[NPIX + p] = S;                      // SoS copy fused here
    float m = mask[p];
    float tv = 0.f;
    if (i > 0) tv += fabsf((S - d_SoS[p - 512]) * m);
    if (j > 0) tv += fabsf((S - d_SoS[p - 1]) * m);
    float l1 = fabsf(S - 1550.f) * m;
    float t1 = blockReduce(tv);
    if (threadIdx.x == 0) atomicAdd(&d_acc[1], (double)t1);
    float t2 = blockReduce(l1);
    if (threadIdx.x == 0) atomicAdd(&d_acc[2], (double)t2);
}

__global__ void k_final(float* __restrict__ out){
    double data = d_acc[0] / (double)((size_t)ND * NPIX);
    double loss = data + 0.001 * d_acc[1] + 0.001 * (d_acc[2] / (double)NPIX);
    out[2 * NPIX] = (float)loss;
}

// ---------------- launch ----------------
extern "C" void kernel_launch(void* const* d_in, const int* in_sizes, int n_in,
                              void* d_out, int out_size){
    const float* W1  = (const float*)d_in[0];
    const float* b1  = (const float*)d_in[1];
    const float* W2  = (const float*)d_in[2];
    const float* b2  = (const float*)d_in[3];
    const float* W3  = (const float*)d_in[4];
    const float* b3  = (const float*)d_in[5];
    const float* W4  = (const float*)d_in[6];
    const float* b4  = (const float*)d_in[7];
    const float* y_img   = (const float*)d_in[8];
    const float* delays  = (const float*)d_in[9];
    const float* xq      = (const float*)d_in[10];
    const float* yq      = (const float*)d_in[11];
    const float* mgrid   = (const float*)d_in[12];
    const float* mask    = (const float*)d_in[13];
    const int*   mask_idx= (const int*)  d_in[14];
    const float* x_vec   = (const float*)d_in[15];
    const float* y_vec   = (const float*)d_in[16];
    int M = in_sizes[14];
    if (M > MAXM) M = MAXM;
    float* out = (float*)d_out;

    k_prep<<<NPIX/256, 256>>>();

    // SIREN
    k_siren1<<<M, 128>>>(mgrid, W1, b1, M);
    k_mid<<<(M + 63) / 64, 256>>>(W2, b2, M, 0);     // hA -> hB
    k_mid<<<(M + 63) / 64, 256>>>(W3, b3, M, 1);     // hB -> hA
    k_siren_out<<<(M + 3) / 4, 128>>>(W4, b4, mask_idx, M);

    // wavefront
    k_wavefront<<<NTH, 256>>>(xq, yq, x_vec, y_vec);

    // Y = fft2(ifftshift(pad(y*GWIN)))  (zero rows skipped, real rows packed,
    // only rows 0..256 stored) — radix-4 Stockham
    k_fft_rows_Y<<<ND*128, 128>>>(y_img);
    k_fft_cols_Y<<<ND*128, dim3(4, 128)>>>();

    // fused H + Wiener solve + data loss (half-plane + exact Nyquist handling)
    k_solve<<<515, 256>>>(delays);

    // reconstruction (radix-4 Stockham)
    k_ifft_rows<<<512, 128>>>();
    k_ifft_cols_out<<<128, dim3(4, 128)>>>(out);

    // losses + SoS copy
    k_tv_l1<<<NPIX/256, 256>>>(mask, out);
    k_final<<<1, 1>>>(out);
}